// round 13
// baseline (speedup 1.0000x reference)
#include <cuda_runtime.h>
#include <cuda_bf16.h>
#include <math.h>

#define Bn 4
#define KH 4
#define Cd 512
#define Dd 512
#define Nn 1024
#define NHh 8
#define QDq 64
#define THETAF (6.2831853071795865f / 1024.0f)
#define OUT_ELEMS 8388608

#define MT 128
#define NT 64
#define KT 16

// dynamic smem layout per buffer (floats): Ar 16*132, Ai 16*132, Br 16*64, Bi 16*64
#define BUF_F 6272
#define AR_O 0
#define AI_O 2112
#define BR_O 4224
#define BI_O 5248
#define K12_SMEM (2*BUF_F*4)   // 50176 bytes

// ---------------- scratch (all batches; ~395 MB) -----------------------------
__device__ float g_Er[(size_t)Bn*3*KH*Dd*Nn];
__device__ float g_Ei[(size_t)Bn*3*KH*Dd*Nn];
__device__ float g_S [(size_t)Bn*NHh*Nn*Nn];
__device__ float g_Pr[Bn*KH*NHh*Nn];
__device__ float g_Pi[Bn*KH*NHh*Nn];
__device__ float g_ctxr[(size_t)Bn*KH*Cd*Nn];
__device__ float g_ctxi[(size_t)Bn*KH*Cd*Nn];

typedef unsigned long long u64;
typedef unsigned int u32;
union F4U { float4 f; u64 u[2]; };

#define PK2(d, x) asm("mov.b64 %0, {%1, %1};" : "=l"(d) : "f"(x))
#define FMA2(d, a, b) asm("fma.rn.f32x2 %0, %1, %2, %0;" : "+l"(d) : "l"(a), "l"(b))

static __device__ __forceinline__ float2 unp2(u64 v) {
    float2 r; asm("mov.b64 {%0, %1}, %2;" : "=f"(r.x), "=f"(r.y) : "l"(v)); return r;
}
static __device__ __forceinline__ float ldin(const float* p, int off, int n) {
    return (off >= 0 && off < n) ? p[off] : 0.0f;
}
static __device__ __forceinline__ u32 smem_u32(const void* p) {
    u32 a; asm("{ .reg .u64 t; cvta.to.shared.u64 t, %1; cvt.u32.u64 %0, t; }"
               : "=r"(a) : "l"(p));
    return a;
}

// ---------------- mma.sync helpers ------------------------------------------
#define LDSM4(r, a) asm volatile( \
    "ldmatrix.sync.aligned.m8n8.x4.shared.b16 {%0,%1,%2,%3}, [%4];" \
    : "=r"((r)[0]),"=r"((r)[1]),"=r"((r)[2]),"=r"((r)[3]) : "r"(a))
#define LDSM2T(r, a) asm volatile( \
    "ldmatrix.sync.aligned.m8n8.x2.trans.shared.b16 {%0,%1}, [%2];" \
    : "=r"((r)[0]),"=r"((r)[1]) : "r"(a))
#define MMABF(d, a, b) asm volatile( \
    "mma.sync.aligned.m16n8k16.row.col.f32.bf16.bf16.f32 " \
    "{%0,%1,%2,%3},{%4,%5,%6,%7},{%8,%9},{%0,%1,%2,%3};" \
    : "+f"((d)[0]),"+f"((d)[1]),"+f"((d)[2]),"+f"((d)[3]) \
    : "r"((a)[0]),"r"((a)[1]),"r"((a)[2]),"r"((a)[3]),"r"((b)[0]),"r"((b)[1]))

static __device__ __forceinline__ unsigned short bfh(float v) {
    __nv_bfloat16 h = __float2bfloat16(v);
    return *(unsigned short*)&h;
}
static __device__ __forceinline__ float bf2f(unsigned short s) {
    __nv_bfloat16 h = *(__nv_bfloat16*)&s;
    return __bfloat162float(h);
}
static __device__ __forceinline__ void split2(float v, unsigned short* o) {
    unsigned short h = bfh(v);
    o[0] = h; o[1] = bfh(v - bf2f(h));
}

#define APL 10240
#define BPL 8704
#define K4_SMEM (4*APL + 2*BPL)
#define K5_SMEM (4*APL + 4*BPL)

// ---- k1 (FFMA2, double-buffered): E[b,e,k,d,n] = sum_c emb*x ---------------
__global__ void __launch_bounds__(256, 2)
k1_embed(const float* __restrict__ embr, const float* __restrict__ embi,
         const float* __restrict__ xr,   const float* __restrict__ xi,
         const float* __restrict__ softr,const float* __restrict__ softi)
{
    extern __shared__ float sh[];
    int z = blockIdx.z;
    int b = z / 12, r12 = z % 12, e = r12 / KH, k = r12 % KH;
    const float* Ar_ = embr + (size_t)(e*KH + k)*Dd*Cd;
    const float* Ai_ = embi + (size_t)(e*KH + k)*Dd*Cd;
    const float* Br_ = xr + (size_t)(b*KH + k)*Cd*Nn;
    const float* Bi_ = xi + (size_t)(b*KH + k)*Cd*Nn;
    int m0 = blockIdx.y*MT, n0 = blockIdx.x*NT;
    int tid = threadIdx.x, tx = tid & 15, ty = tid >> 4;
    u64 crp[4][4] = {}, cip[4][4] = {};

    int am[2], akc[2];
    #pragma unroll
    for (int i2 = 0; i2 < 2; i2++) { int g = tid + i2*256; am[i2] = g >> 2; akc[i2] = (g & 3)*4; }
    int bkk = tid >> 4, bnc = (tid & 15)*4;

    float4 par[2], pai[2], pbr, pbi;
    #pragma unroll
    for (int i2 = 0; i2 < 2; i2++) {
        par[i2] = *(const float4*)&Ar_[(size_t)(m0+am[i2])*Cd + akc[i2]];
        pai[i2] = *(const float4*)&Ai_[(size_t)(m0+am[i2])*Cd + akc[i2]];
    }
    pbr = *(const float4*)&Br_[(size_t)bkk*Nn + n0 + bnc];
    pbi = *(const float4*)&Bi_[(size_t)bkk*Nn + n0 + bnc];
    {
        float* As_r = sh + AR_O; float* As_i = sh + AI_O;
        float* Bs_r = sh + BR_O; float* Bs_i = sh + BI_O;
        #pragma unroll
        for (int i2 = 0; i2 < 2; i2++) {
            float a[4] = {par[i2].x,par[i2].y,par[i2].z,par[i2].w};
            float c[4] = {pai[i2].x,pai[i2].y,pai[i2].z,pai[i2].w};
            #pragma unroll
            for (int j = 0; j < 4; j++) {
                As_r[(akc[i2]+j)*132 + am[i2]] = a[j];
                As_i[(akc[i2]+j)*132 + am[i2]] = c[j];
            }
        }
        *(float4*)&Bs_r[bkk*64 + bnc] = pbr;
        *(float4*)&Bs_i[bkk*64 + bnc] = pbi;
    }
    __syncthreads();

    const int NIT = Cd / KT;
    for (int itc = 0; itc < NIT; itc++) {
        int buf = itc & 1;
        if (itc + 1 < NIT) {
            int c0 = (itc+1)*KT;
            #pragma unroll
            for (int i2 = 0; i2 < 2; i2++) {
                par[i2] = *(const float4*)&Ar_[(size_t)(m0+am[i2])*Cd + c0 + akc[i2]];
                pai[i2] = *(const float4*)&Ai_[(size_t)(m0+am[i2])*Cd + c0 + akc[i2]];
            }
            pbr = *(const float4*)&Br_[(size_t)(c0+bkk)*Nn + n0 + bnc];
            pbi = *(const float4*)&Bi_[(size_t)(c0+bkk)*Nn + n0 + bnc];
        }
        const float* As_r = sh + buf*BUF_F + AR_O;
        const float* As_i = sh + buf*BUF_F + AI_O;
        const float* Bs_r = sh + buf*BUF_F + BR_O;
        const float* Bs_i = sh + buf*BUF_F + BI_O;
        #pragma unroll
        for (int kk = 0; kk < KT; kk++) {
            F4U ar0, ar1, ai0, ai1;
            ar0.f = *(const float4*)&As_r[kk*132 + ty*8];
            ar1.f = *(const float4*)&As_r[kk*132 + ty*8+4];
            ai0.f = *(const float4*)&As_i[kk*132 + ty*8];
            ai1.f = *(const float4*)&As_i[kk*132 + ty*8+4];
            u64 apr[4] = {ar0.u[0], ar0.u[1], ar1.u[0], ar1.u[1]};
            u64 api[4] = {ai0.u[0], ai0.u[1], ai1.u[0], ai1.u[1]};
            float4 brv = *(const float4*)&Bs_r[kk*64 + tx*4];
            float4 biv = *(const float4*)&Bs_i[kk*64 + tx*4];
            float brs[4] = {brv.x,brv.y,brv.z,brv.w};
            float bis[4] = {biv.x,biv.y,biv.z,biv.w};
            #pragma unroll
            for (int j = 0; j < 4; j++) {
                u64 bpr, bpi, bpn;
                PK2(bpr, brs[j]); PK2(bpi, bis[j]);
                float nb = -bis[j]; PK2(bpn, nb);
                #pragma unroll
                for (int mi = 0; mi < 4; mi++) {
                    FMA2(crp[mi][j], apr[mi], bpr);
                    FMA2(crp[mi][j], api[mi], bpn);
                    FMA2(cip[mi][j], apr[mi], bpi);
                    FMA2(cip[mi][j], api[mi], bpr);
                }
            }
        }
        if (itc + 1 < NIT) {
            float* As_r = sh + (buf^1)*BUF_F + AR_O;
            float* As_i = sh + (buf^1)*BUF_F + AI_O;
            float* Bs_r = sh + (buf^1)*BUF_F + BR_O;
            float* Bs_i = sh + (buf^1)*BUF_F + BI_O;
            #pragma unroll
            for (int i2 = 0; i2 < 2; i2++) {
                float a[4] = {par[i2].x,par[i2].y,par[i2].z,par[i2].w};
                float c[4] = {pai[i2].x,pai[i2].y,pai[i2].z,pai[i2].w};
                #pragma unroll
                for (int j = 0; j < 4; j++) {
                    As_r[(akc[i2]+j)*132 + am[i2]] = a[j];
                    As_i[(akc[i2]+j)*132 + am[i2]] = c[j];
                }
            }
            *(float4*)&Bs_r[bkk*64 + bnc] = pbr;
            *(float4*)&Bs_i[bkk*64 + bnc] = pbi;
        }
        __syncthreads();
    }

    float* Eor = g_Er + ((size_t)(b*3 + e)*KH + k)*Dd*Nn;
    float* Eoi = g_Ei + ((size_t)(b*3 + e)*KH + k)*Dd*Nn;
    #pragma unroll
    for (int r = 0; r < 8; r++) {
        int m = m0 + ty*8 + r, mi = r >> 1, hi = r & 1;
        float sr = 1.f, si = 0.f;
        if (e == 1) { int h = m >> 6; sr = softr[k*NHh+h]; si = softi[k*NHh+h]; }
        float vr[4], vi[4];
        #pragma unroll
        for (int j = 0; j < 4; j++) {
            float2 c2r = unp2(crp[mi][j]), c2i = unp2(cip[mi][j]);
            float cr = hi ? c2r.y : c2r.x, ci = hi ? c2i.y : c2i.x;
            vr[j] = cr*sr - ci*si; vi[j] = cr*si + ci*sr;
        }
        *(float4*)&Eor[(size_t)m*Nn + n0 + tx*4] = make_float4(vr[0],vr[1],vr[2],vr[3]);
        *(float4*)&Eoi[(size_t)m*Nn + n0 + tx*4] = make_float4(vi[0],vi[1],vi[2],vi[3]);
    }
}

// ---- kP (all b) --------------------------------------------------------------
__global__ void kP_pos(const float* __restrict__ encr, const float* __restrict__ enci,
                       const float* __restrict__ softr,const float* __restrict__ softi,
                       int n_encr, int n_enci, int n_softr, int n_softi)
{
    int y = blockIdx.y;
    int b = y / (KH*NHh), k = (y / NHh) % KH, h = y % NHh;
    int i = blockIdx.x*256 + threadIdx.x;
    size_t e0 = (size_t)(b*3)*KH*Dd*Nn + (size_t)(k*Dd + h*QDq)*Nn;
    const float* E0r = g_Er + e0;
    const float* E0i = g_Ei + e0;
    float accr = 0.f, acci = 0.f;
    for (int q = 0; q < QDq; q++) {
        float er = E0r[(size_t)q*Nn + i], ei = E0i[(size_t)q*Nn + i];
        float nr = ldin(encr, (k*NHh + h)*QDq + q, n_encr);
        float ni = ldin(enci, (k*NHh + h)*QDq + q, n_enci);
        accr += er*nr + ei*ni;
        acci += er*ni - ei*nr;
    }
    float sr = ldin(softr, k*NHh + h, n_softr);
    float si = ldin(softi, k*NHh + h, n_softi);
    float tr = accr*sr - acci*si, ti = accr*si + acci*sr;
    float s, c;
    sincosf(THETAF * (float)(k*i), &s, &c);
    int o = ((b*KH + k)*NHh + h)*Nn + i;
    g_Pr[o] = tr*c - ti*s;
    g_Pi[o] = tr*s + ti*c;
}

// ---- k2 (FFMA2, double-buffered): S = |GEMM + pos| / 8 ----------------------
__global__ void __launch_bounds__(256, 2) k2_scores()
{
    extern __shared__ float sh[];
    int z = blockIdx.z;
    int b = z >> 3, h = z & 7;
    int i0 = blockIdx.y*MT, j0 = blockIdx.x*NT;
    int tid = threadIdx.x, tx = tid & 15, ty = tid >> 4;
    const float* E1r = g_Er + (size_t)(b*3 + 1)*KH*Dd*Nn;
    const float* E1i = g_Ei + (size_t)(b*3 + 1)*KH*Dd*Nn;
    const float* E0r = g_Er + (size_t)(b*3)*KH*Dd*Nn;
    const float* E0i = g_Ei + (size_t)(b*3)*KH*Dd*Nn;
    u64 crp[4][4] = {}, cip[4][4] = {};

    int alk[2], aic[2];
    #pragma unroll
    for (int i2 = 0; i2 < 2; i2++) { int g = tid + i2*256; alk[i2] = g >> 5; aic[i2] = (g & 31)*4; }
    int bkk = tid >> 4, bnc = (tid & 15)*4;

    float4 par[2], pai[2], pbr, pbi;
    #pragma unroll
    for (int i2 = 0; i2 < 2; i2++) {
        int l = alk[i2], kq = l >> 6, q = l & 63;
        size_t ro = (size_t)(kq*Dd + h*QDq + q)*Nn;
        par[i2] = *(const float4*)&E1r[ro + i0 + aic[i2]];
        pai[i2] = *(const float4*)&E1i[ro + i0 + aic[i2]];
    }
    {
        int l = bkk, kq = l >> 6, q = l & 63;
        size_t ro = (size_t)(kq*Dd + h*QDq + q)*Nn;
        pbr = *(const float4*)&E0r[ro + j0 + bnc];
        pbi = *(const float4*)&E0i[ro + j0 + bnc];
    }
    {
        float* As_r = sh + AR_O; float* As_i = sh + AI_O;
        float* Bs_r = sh + BR_O; float* Bs_i = sh + BI_O;
        #pragma unroll
        for (int i2 = 0; i2 < 2; i2++) {
            *(float4*)&As_r[alk[i2]*132 + aic[i2]] = par[i2];
            *(float4*)&As_i[alk[i2]*132 + aic[i2]] = pai[i2];
        }
        *(float4*)&Bs_r[bkk*64 + bnc] = pbr;
        *(float4*)&Bs_i[bkk*64 + bnc] = make_float4(-pbi.x,-pbi.y,-pbi.z,-pbi.w);
    }
    __syncthreads();

    const int NIT = (KH*QDq) / KT;   // 16
    for (int itc = 0; itc < NIT; itc++) {
        int buf = itc & 1;
        if (itc + 1 < NIT) {
            int l0 = (itc+1)*KT;
            #pragma unroll
            for (int i2 = 0; i2 < 2; i2++) {
                int l = l0 + alk[i2], kq = l >> 6, q = l & 63;
                size_t ro = (size_t)(kq*Dd + h*QDq + q)*Nn;
                par[i2] = *(const float4*)&E1r[ro + i0 + aic[i2]];
                pai[i2] = *(const float4*)&E1i[ro + i0 + aic[i2]];
            }
            int l = l0 + bkk, kq = l >> 6, q = l & 63;
            size_t ro = (size_t)(kq*Dd + h*QDq + q)*Nn;
            pbr = *(const float4*)&E0r[ro + j0 + bnc];
            pbi = *(const float4*)&E0i[ro + j0 + bnc];
        }
        const float* As_r = sh + buf*BUF_F + AR_O;
        const float* As_i = sh + buf*BUF_F + AI_O;
        const float* Bs_r = sh + buf*BUF_F + BR_O;
        const float* Bs_i = sh + buf*BUF_F + BI_O;
        #pragma unroll
        for (int kk = 0; kk < KT; kk++) {
            F4U ar0, ar1, ai0, ai1;
            ar0.f = *(const float4*)&As_r[kk*132 + ty*8];
            ar1.f = *(const float4*)&As_r[kk*132 + ty*8+4];
            ai0.f = *(const float4*)&As_i[kk*132 + ty*8];
            ai1.f = *(const float4*)&As_i[kk*132 + ty*8+4];
            u64 apr[4] = {ar0.u[0], ar0.u[1], ar1.u[0], ar1.u[1]};
            u64 api[4] = {ai0.u[0], ai0.u[1], ai1.u[0], ai1.u[1]};
            float4 brv = *(const float4*)&Bs_r[kk*64 + tx*4];
            float4 biv = *(const float4*)&Bs_i[kk*64 + tx*4];
            float brs[4] = {brv.x,brv.y,brv.z,brv.w};
            float bis[4] = {biv.x,biv.y,biv.z,biv.w};
            #pragma unroll
            for (int j = 0; j < 4; j++) {
                u64 bpr, bpi, bpn;
                PK2(bpr, brs[j]); PK2(bpi, bis[j]);
                float nb = -bis[j]; PK2(bpn, nb);
                #pragma unroll
                for (int mi = 0; mi < 4; mi++) {
                    FMA2(crp[mi][j], apr[mi], bpr);
                    FMA2(crp[mi][j], api[mi], bpn);
                    FMA2(cip[mi][j], apr[mi], bpi);
                    FMA2(cip[mi][j], api[mi], bpr);
                }
            }
        }
        if (itc + 1 < NIT) {
            float* As_r = sh + (buf^1)*BUF_F + AR_O;
            float* As_i = sh + (buf^1)*BUF_F + AI_O;
            float* Bs_r = sh + (buf^1)*BUF_F + BR_O;
            float* Bs_i = sh + (buf^1)*BUF_F + BI_O;
            #pragma unroll
            for (int i2 = 0; i2 < 2; i2++) {
                *(float4*)&As_r[alk[i2]*132 + aic[i2]] = par[i2];
                *(float4*)&As_i[alk[i2]*132 + aic[i2]] = pai[i2];
            }
            *(float4*)&Bs_r[bkk*64 + bnc] = pbr;
            *(float4*)&Bs_i[bkk*64 + bnc] = make_float4(-pbi.x,-pbi.y,-pbi.z,-pbi.w);
        }
        __syncthreads();
    }

    // pos epilogue
    #pragma unroll
    for (int j = 0; j < 4; j++) {
        int jj = j0 + tx*4 + j;
        float s, c;
        sincosf(-THETAF * (float)jj, &s, &c);
        float wr = c, wi = s, curr = 1.f, curi = 0.f;
        #pragma unroll
        for (int kq = 0; kq < KH; kq++) {
            u64 cp, sp, sn;
            PK2(cp, curr); PK2(sp, curi);
            float ns = -curi; PK2(sn, ns);
            #pragma unroll
            for (int mi = 0; mi < 4; mi++) {
                int i = i0 + ty*8 + mi*2;
                int off = ((b*KH + kq)*NHh + h)*Nn + i;
                u64 ppr = *(const u64*)&g_Pr[off];
                u64 ppi = *(const u64*)&g_Pi[off];
                FMA2(crp[mi][j], ppr, cp);
                FMA2(crp[mi][j], ppi, sn);
                FMA2(cip[mi][j], ppr, sp);
                FMA2(cip[mi][j], ppi, cp);
            }
            float nr = curr*wr - curi*wi;
            curi = curr*wi + curi*wr;
            curr = nr;
        }
    }
    float* So = g_S + (size_t)(b*NHh + h)*Nn*Nn;
    #pragma unroll
    for (int r = 0; r < 8; r++) {
        int i = i0 + ty*8 + r, mi = r >> 1, hi = r & 1;
        float sv[4];
        #pragma unroll
        for (int j = 0; j < 4; j++) {
            float2 c2r = unp2(crp[mi][j]), c2i = unp2(cip[mi][j]);
            float cr = hi ? c2r.y : c2r.x, ci = hi ? c2i.y : c2i.x;
            sv[j] = sqrtf(cr*cr + ci*ci) * 0.125f;
        }
        *(float4*)&So[(size_t)i*Nn + j0 + tx*4] = make_float4(sv[0],sv[1],sv[2],sv[3]);
    }
}

// ---- k3 (all b): softmax over i, per (b,h,j) ---------------------------------
__global__ void k3_softmax()
{
    __shared__ __align__(16) float red[8][33];
    int y = blockIdx.y;
    int b = y >> 3, h = y & 7;
    int tx = threadIdx.x, ty = threadIdx.y;
    int j = blockIdx.x*32 + tx;
    size_t base = (size_t)(b*NHh + h)*Nn*Nn;
    float mx = -1e30f;
    for (int i = ty; i < Nn; i += 8)
        mx = fmaxf(mx, g_S[base + (size_t)i*Nn + j]);
    red[ty][tx] = mx;
    __syncthreads();
    if (ty == 0) {
        float m = red[0][tx];
        #pragma unroll
        for (int r = 1; r < 8; r++) m = fmaxf(m, red[r][tx]);
        red[0][tx] = m;
    }
    __syncthreads();
    mx = red[0][tx];
    __syncthreads();
    float sum = 0.f;
    for (int i = ty; i < Nn; i += 8) {
        size_t o = base + (size_t)i*Nn + j;
        float e = expf(g_S[o] - mx);
        g_S[o] = e;
        sum += e;
    }
    red[ty][tx] = sum;
    __syncthreads();
    if (ty == 0) {
        float s = red[0][tx];
        #pragma unroll
        for (int r = 1; r < 8; r++) s += red[r][tx];
        red[0][tx] = s;
    }
    __syncthreads();
    float inv = 1.0f / red[0][tx];
    for (int i = ty; i < Nn; i += 8)
        g_S[base + (size_t)i*Nn + j] *= inv;
}

// ---- k4 (mma 2-split): ctx = V @ S ------------------------------------------
__global__ void __launch_bounds__(512, 1) k4_mma()
{
    extern __shared__ char sm[];
    u32 smA = smem_u32(sm);
    u32 smB = smA + 4*APL;
    int tid = threadIdx.x, wid = tid >> 5, lane = tid & 31;
    int wm = wid >> 2, wn = wid & 3;
    int z = blockIdx.z, b = z >> 3, h = z & 7;
    int m0 = blockIdx.y*128, j0 = blockIdx.x*128;
    const float* Vr = g_Er + (size_t)(b*3 + 2)*KH*Dd*Nn;
    const float* Vi = g_Ei + (size_t)(b*3 + 2)*KH*Dd*Nn;
    const float* S  = g_S + (size_t)(b*NHh + h)*Nn*Nn;
    const int PA2[3] = {0, 0, 1};
    const int PB2[3] = {0, 1, 0};
    float dr[2][4][4] = {}, di[2][4][4] = {};
    u32 aRowOff = (u32)((wm*32 + (lane & 15))*80 + (lane >> 4)*16);
    u32 bColOff = (u32)(wn*64);

    for (int c0 = 0; c0 < Nn; c0 += 32) {
        #pragma unroll
        for (int it = 0; it < 2; it++) {
            int t = tid + it*512;
            int m = t >> 3, c4 = (t & 7)*4;
            int l = m0 + m, kq = l >> 6, q = l & 63;
            size_t ro = (size_t)(kq*Dd + h*QDq + q)*Nn;
            float4 vr = *(const float4*)&Vr[ro + c0 + c4];
            float4 vi = *(const float4*)&Vi[ro + c0 + c4];
            unsigned short hh[4], ll[4], s2[2];
            u32 wo = (u32)(m*80 + c4*2);
            float rs[4] = {vr.x, vr.y, vr.z, vr.w};
            #pragma unroll
            for (int j = 0; j < 4; j++) { split2(rs[j], s2); hh[j]=s2[0]; ll[j]=s2[1]; }
            *(u64*)(sm + 0*APL + wo) = (u64)hh[0] | ((u64)hh[1]<<16) | ((u64)hh[2]<<32) | ((u64)hh[3]<<48);
            *(u64*)(sm + 1*APL + wo) = (u64)ll[0] | ((u64)ll[1]<<16) | ((u64)ll[2]<<32) | ((u64)ll[3]<<48);
            float is[4] = {vi.x, vi.y, vi.z, vi.w};
            #pragma unroll
            for (int j = 0; j < 4; j++) { split2(is[j], s2); hh[j]=s2[0]; ll[j]=s2[1]; }
            *(u64*)(sm + 2*APL + wo) = (u64)hh[0] | ((u64)hh[1]<<16) | ((u64)hh[2]<<32) | ((u64)hh[3]<<48);
            *(u64*)(sm + 3*APL + wo) = (u64)ll[0] | ((u64)ll[1]<<16) | ((u64)ll[2]<<32) | ((u64)ll[3]<<48);
        }
        #pragma unroll
        for (int it = 0; it < 2; it++) {
            int t = tid + it*512;
            int c = t >> 5, n4 = (t & 31)*4;
            float4 sv = *(const float4*)&S[(size_t)(c0 + c)*Nn + j0 + n4];
            unsigned short hh[4], ll[4], s2[2];
            u32 wo = (u32)(c*272 + n4*2);
            float ss[4] = {sv.x, sv.y, sv.z, sv.w};
            #pragma unroll
            for (int j = 0; j < 4; j++) { split2(ss[j], s2); hh[j]=s2[0]; ll[j]=s2[1]; }
            char* bb = sm + 4*APL;
            *(u64*)(bb + 0*BPL + wo) = (u64)hh[0] | ((u64)hh[1]<<16) | ((u64)hh[2]<<32) | ((u64)hh[3]<<48);
            *(u64*)(bb + 1*BPL + wo) = (u64)ll[0] | ((u64)ll[1]<<16) | ((u64)ll[2]<<32) | ((u64)ll[3]<<48);
        }
        __syncthreads();
        #pragma unroll
        for (int ks = 0; ks < 2; ks++) {
            #pragma unroll
            for (int s = 0; s < 3; s++) {
                u32 ar0[4], ar1[4], ai0[4], ai1[4];
                u32 abase = smA + aRowOff + (u32)(ks*32);
                LDSM4(ar0, abase + PA2[s]*APL);
                LDSM4(ar1, abase + PA2[s]*APL + 16*80);
                LDSM4(ai0, abase + (2+PA2[s])*APL);
                LDSM4(ai1, abase + (2+PA2[s])*APL + 16*80);
                u32 bbase = smB + (u32)((ks*16 + (lane & 15))*272) + bColOff;
                #pragma unroll
                for (int nt = 0; nt < 4; nt++) {
                    u32 bb[2];
                    LDSM2T(bb, bbase + (u32)(nt*16) + PB2[s]*BPL);
                    MMABF(dr[0][nt], ar0, bb); MMABF(di[0][nt], ai0, bb);
                    MMABF(dr[1][nt], ar1, bb); MMABF(di[1][nt], ai1, bb);
                }
            }
        }
        __syncthreads();
    }
    size_t cb = (size_t)b*KH*Cd*Nn;
    #pragma unroll
    for (int mt = 0; mt < 2; mt++) {
        #pragma unroll
        for (int ch = 0; ch < 2; ch++) {
            int l = m0 + wm*32 + mt*16 + (lane >> 2) + ch*8;
            int kq = l >> 6, q = l & 63;
            size_t ro = cb + (size_t)(kq*Cd + h*QDq + q)*Nn;
            #pragma unroll
            for (int nt = 0; nt < 4; nt++) {
                int j = j0 + wn*32 + nt*8 + (lane & 3)*2;
                *(float2*)&g_ctxr[ro + j] = make_float2(dr[mt][nt][ch*2], dr[mt][nt][ch*2+1]);
                *(float2*)&g_ctxi[ro + j] = make_float2(di[mt][nt][ch*2], di[mt][nt][ch*2+1]);
            }
        }
    }
}

// ---- k5 (mma 2-split, real-only): res = Re(out @ ctx) ------------------------
__global__ void __launch_bounds__(512, 1)
k5_mma(const float* __restrict__ outr, const float* __restrict__ outi,
       float* __restrict__ res, int n_res)
{
    extern __shared__ char sm[];
    u32 smA = smem_u32(sm);
    u32 smB = smA + 4*APL;
    int tid = threadIdx.x, wid = tid >> 5, lane = tid & 31;
    int wm = wid >> 2, wn = wid & 3;
    int z = blockIdx.z, b = z >> 2, k = z & 3;
    int m0 = blockIdx.y*128, j0 = blockIdx.x*128;
    const float* Ar = outr + (size_t)k*Dd*Cd;
    const float* Ai = outi + (size_t)k*Dd*Cd;
    const float* Br = g_ctxr + ((size_t)b*KH + k)*Cd*Nn;
    const float* Bi = g_ctxi + ((size_t)b*KH + k)*Cd*Nn;
    const int PA2[3] = {0, 0, 1};
    const int PB2[3] = {0, 1, 0};
    float dr[2][4][4] = {};
    u32 aRowOff = (u32)((wm*32 + (lane & 15))*80 + (lane >> 4)*16);
    u32 bColOff = (u32)(wn*64);

    for (int c0 = 0; c0 < Cd; c0 += 32) {
        #pragma unroll
        for (int it = 0; it < 2; it++) {
            int t = tid + it*512;
            int m = t >> 3, c4 = (t & 7)*4;
            float4 vr = *(const float4*)&Ar[(size_t)(m0+m)*Cd + c0 + c4];
            float4 vi = *(const float4*)&Ai[(size_t)(m0+m)*Cd + c0 + c4];
            unsigned short hh[4], ll[4], s2[2];
            u32 wo = (u32)(m*80 + c4*2);
            float rs[4] = {vr.x, vr.y, vr.z, vr.w};
            #pragma unroll
            for (int j = 0; j < 4; j++) { split2(rs[j], s2); hh[j]=s2[0]; ll[j]=s2[1]; }
            *(u64*)(sm + 0*APL + wo) = (u64)hh[0] | ((u64)hh[1]<<16) | ((u64)hh[2]<<32) | ((u64)hh[3]<<48);
            *(u64*)(sm + 1*APL + wo) = (u64)ll[0] | ((u64)ll[1]<<16) | ((u64)ll[2]<<32) | ((u64)ll[3]<<48);
            float is[4] = {-vi.x, -vi.y, -vi.z, -vi.w};
            #pragma unroll
            for (int j = 0; j < 4; j++) { split2(is[j], s2); hh[j]=s2[0]; ll[j]=s2[1]; }
            *(u64*)(sm + 2*APL + wo) = (u64)hh[0] | ((u64)hh[1]<<16) | ((u64)hh[2]<<32) | ((u64)hh[3]<<48);
            *(u64*)(sm + 3*APL + wo) = (u64)ll[0] | ((u64)ll[1]<<16) | ((u64)ll[2]<<32) | ((u64)ll[3]<<48);
        }
        #pragma unroll
        for (int it = 0; it < 2; it++) {
            int t = tid + it*512;
            int c = t >> 5, n4 = (t & 31)*4;
            size_t go = (size_t)(c0 + c)*Nn + j0 + n4;
            float4 vr = *(const float4*)&Br[go];
            float4 vi = *(const float4*)&Bi[go];
            unsigned short hh[4], ll[4], s2[2];
            u32 wo = (u32)(c*272 + n4*2);
            char* bb = sm + 4*APL;
            float rs[4] = {vr.x, vr.y, vr.z, vr.w};
            #pragma unroll
            for (int j = 0; j < 4; j++) { split2(rs[j], s2); hh[j]=s2[0]; ll[j]=s2[1]; }
            *(u64*)(bb + 0*BPL + wo) = (u64)hh[0] | ((u64)hh[1]<<16) | ((u64)hh[2]<<32) | ((u64)hh[3]<<48);
            *(u64*)(bb + 1*BPL + wo) = (u64)ll[0] | ((u64)ll[1]<<16) | ((u64)ll[2]<<32) | ((u64)ll[3]<<48);
            float is[4] = {vi.x, vi.y, vi.z, vi.w};
            #pragma unroll
            for (int j = 0; j < 4; j++) { split2(is[j], s2); hh[j]=s2[0]; ll[j]=s2[1]; }
            *(u64*)(bb + 2*BPL + wo) = (u64)hh[0] | ((u64)hh[1]<<16) | ((u64)hh[2]<<32) | ((u64)hh[3]<<48);
            *(u64*)(bb + 3*BPL + wo) = (u64)ll[0] | ((u64)ll[1]<<16) | ((u64)ll[2]<<32) | ((u64)ll[3]<<48);
        }
        __syncthreads();
        #pragma unroll
        for (int ks = 0; ks < 2; ks++) {
            #pragma unroll
            for (int s = 0; s < 3; s++) {
                u32 ar0[4], ar1[4], an0[4], an1[4];
                u32 abase = smA + aRowOff + (u32)(ks*32);
                LDSM4(ar0, abase + PA2[s]*APL);
                LDSM4(ar1, abase + PA2[s]*APL + 16*80);
                LDSM4(an0, abase + (2+PA2[s])*APL);
                LDSM4(an1, abase + (2+PA2[s])*APL + 16*80);
                u32 bbase = smB + (u32)((ks*16 + (lane & 15))*272) + bColOff;
                #pragma unroll
                for (int nt = 0; nt < 4; nt++) {
                    u32 br[2], bi2[2];
                    u32 boff = bbase + (u32)(nt*16);
                    LDSM2T(br, boff + PB2[s]*BPL);
                    LDSM2T(bi2, boff + (2+PB2[s])*BPL);
                    MMABF(dr[0][nt], ar0, br); MMABF(dr[0][nt], an0, bi2);
                    MMABF(dr[1][nt], ar1, br); MMABF(dr[1][nt], an1, bi2);
                }
            }
        }
        __syncthreads();
    }
    int nlim = n_res < OUT_ELEMS ? n_res : OUT_ELEMS;
    #pragma unroll
    for (int mt = 0; mt < 2; mt++) {
        #pragma unroll
        for (int ch = 0; ch < 2; ch++) {
            int d = m0 + wm*32 + mt*16 + (lane >> 2) + ch*8;
            size_t row = ((size_t)(b*KH + k)*Dd + d)*Nn;
            #pragma unroll
            for (int nt = 0; nt < 4; nt++) {
                int j = j0 + wn*32 + nt*8 + (lane & 3)*2;
                size_t o = row + j;
                float v0 = dr[mt][nt][ch*2], v1 = dr[mt][nt][ch*2+1];
                if (o + 2 <= (size_t)nlim) {
                    *(float2*)&res[o] = make_float2(v0, v1);
                } else {
                    if (o < (size_t)nlim) res[o] = v0;
                    if (o + 1 < (size_t)nlim) res[o+1] = v1;
                }
            }
        }
    }
}

// ---------------- launch -----------------------------------------------------
static int classify_sz(int sz, int* elems) {
    switch (sz) {
        case 8388608:  *elems = sz;   return 0;
        case 33554432: *elems = sz/4; return 0;
        case 3145728:  *elems = sz;   return 1;
        case 12582912: *elems = sz/4; return 1;
        case 2048:     *elems = sz;   return 2;
        case 8192:     *elems = sz/4; return 2;
        case 32:       *elems = sz;   return 3;
        case 128:      *elems = sz/4; return 3;
        case 1048576:  *elems = sz;   return 4;
        case 4194304:  *elems = sz/4; return 4;
        default: *elems = 0; return -1;
    }
}

extern "C" void kernel_launch(void* const* d_in, const int* in_sizes, int n_in,
                              void* d_out, int out_size)
{
    const float* pairs[5][2] = {};
    int psz[5][2] = {};
    int cnt[5] = {};
    bool ok = (n_in == 10) && d_out;
    if (ok) for (int i = 0; i < n_in; i++) if (!d_in[i]) ok = false;

    if (ok) {
        for (int i = 0; i < n_in; i++) {
            int el; int c = classify_sz(in_sizes[i], &el);
            if (c < 0 || cnt[c] >= 2) { ok = false; break; }
            pairs[c][cnt[c]] = (const float*)d_in[i];
            psz[c][cnt[c]] = el;
            cnt[c]++;
        }
        if (ok) for (int c = 0; c < 5; c++) if (cnt[c] != 2) ok = false;
    }

    const float *xr, *xi, *embr, *embi, *encr, *enci, *softr, *softi, *outr, *outi;
    int nencr, nenci, nsoftr, nsofti;
    if (ok) {
        int el0; int c0 = classify_sz(in_sizes[0], &el0);
        int ri = (c0 == 1) ? 1 : 0;
        int im = 1 - ri;
        xr    = pairs[0][ri]; xi    = pairs[0][im];
        embr  = pairs[1][ri]; embi  = pairs[1][im];
        encr  = pairs[2][ri]; nencr  = psz[2][ri]; enci  = pairs[2][im]; nenci  = psz[2][im];
        softr = pairs[3][ri]; nsoftr = psz[3][ri]; softi = pairs[3][im]; nsofti = psz[3][im];
        outr  = pairs[4][ri]; outi  = pairs[4][im];
    } else if (n_in >= 10 && d_out) {
        xr    = (const float*)d_in[0]; xi    = (const float*)d_in[1];
        embr  = (const float*)d_in[2]; embi  = (const float*)d_in[3];
        encr  = (const float*)d_in[4]; nencr  = in_sizes[4];
        enci  = (const float*)d_in[5]; nenci  = in_sizes[5];
        softr = (const float*)d_in[6]; nsoftr = in_sizes[6];
        softi = (const float*)d_in[7]; nsofti = in_sizes[7];
        outr  = (const float*)d_in[8]; outi  = (const float*)d_in[9];
    } else {
        return;
    }

    cudaFuncSetAttribute(k1_embed, cudaFuncAttributeMaxDynamicSharedMemorySize, K12_SMEM);
    cudaFuncSetAttribute(k2_scores, cudaFuncAttributeMaxDynamicSharedMemorySize, K12_SMEM);
    cudaFuncSetAttribute(k4_mma, cudaFuncAttributeMaxDynamicSharedMemorySize, K4_SMEM);
    cudaFuncSetAttribute(k5_mma, cudaFuncAttributeMaxDynamicSharedMemorySize, K5_SMEM);

    k1_embed<<<dim3(Nn/NT, Dd/MT, 12*Bn), 256, K12_SMEM>>>(embr, embi, xr, xi, softr, softi);
    kP_pos<<<dim3(Nn/256, Bn*KH*NHh), 256>>>(encr, enci, softr, softi,
                                             nencr, nenci, nsoftr, nsofti);
    k2_scores<<<dim3(Nn/NT, Nn/MT, Bn*NHh), 256, K12_SMEM>>>();
    k3_softmax<<<dim3(Nn/32, Bn*NHh), dim3(32, 8)>>>();
    k4_mma<<<dim3(Nn/128, (KH*QDq)/128, Bn*NHh), 512, K4_SMEM>>>();
    k5_mma<<<dim3(Nn/128, Dd/128, Bn*KH), 512, K5_SMEM>>>(outr, outi,
                                                          (float*)d_out, out_size);
}

// round 14
// speedup vs baseline: 1.0300x; 1.0300x over previous
#include <cuda_runtime.h>
#include <cuda_bf16.h>
#include <math.h>

#define Bn 4
#define KH 4
#define Cd 512
#define Dd 512
#define Nn 1024
#define NHh 8
#define QDq 64
#define THETAF (6.2831853071795865f / 1024.0f)
#define OUT_ELEMS 8388608

#define MT 128
#define NT 64
#define KT2 32

// dynamic smem (floats): Ar 32*132, Ai 32*132, Br 32*64, Bi 32*64 = 12544 f
#define AR_O 0
#define AI_O 4224
#define BR_O 8448
#define BI_O 10496
#define K12_SMEM 50176

// ---------------- scratch (all batches; ~395 MB) -----------------------------
__device__ float g_Er[(size_t)Bn*3*KH*Dd*Nn];
__device__ float g_Ei[(size_t)Bn*3*KH*Dd*Nn];
__device__ float g_S [(size_t)Bn*NHh*Nn*Nn];
__device__ float g_Pr[Bn*KH*NHh*Nn];
__device__ float g_Pi[Bn*KH*NHh*Nn];
__device__ float g_inv[Bn*NHh*Nn];
__device__ float g_ctxr[(size_t)Bn*KH*Cd*Nn];
__device__ float g_ctxi[(size_t)Bn*KH*Cd*Nn];

typedef unsigned long long u64;
typedef unsigned int u32;
union F4U { float4 f; u64 u[2]; };

#define PK2(d, x) asm("mov.b64 %0, {%1, %1};" : "=l"(d) : "f"(x))
#define FMA2(d, a, b) asm("fma.rn.f32x2 %0, %1, %2, %0;" : "+l"(d) : "l"(a), "l"(b))

static __device__ __forceinline__ float2 unp2(u64 v) {
    float2 r; asm("mov.b64 {%0, %1}, %2;" : "=f"(r.x), "=f"(r.y) : "l"(v)); return r;
}
static __device__ __forceinline__ float ldin(const float* p, int off, int n) {
    return (off >= 0 && off < n) ? p[off] : 0.0f;
}
static __device__ __forceinline__ u32 smem_u32(const void* p) {
    u32 a; asm("{ .reg .u64 t; cvta.to.shared.u64 t, %1; cvt.u32.u64 %0, t; }"
               : "=r"(a) : "l"(p));
    return a;
}

// ---------------- mma.sync helpers ------------------------------------------
#define LDSM4(r, a) asm volatile( \
    "ldmatrix.sync.aligned.m8n8.x4.shared.b16 {%0,%1,%2,%3}, [%4];" \
    : "=r"((r)[0]),"=r"((r)[1]),"=r"((r)[2]),"=r"((r)[3]) : "r"(a))
#define LDSM2T(r, a) asm volatile( \
    "ldmatrix.sync.aligned.m8n8.x2.trans.shared.b16 {%0,%1}, [%2];" \
    : "=r"((r)[0]),"=r"((r)[1]) : "r"(a))
#define MMABF(d, a, b) asm volatile( \
    "mma.sync.aligned.m16n8k16.row.col.f32.bf16.bf16.f32 " \
    "{%0,%1,%2,%3},{%4,%5,%6,%7},{%8,%9},{%0,%1,%2,%3};" \
    : "+f"((d)[0]),"+f"((d)[1]),"+f"((d)[2]),"+f"((d)[3]) \
    : "r"((a)[0]),"r"((a)[1]),"r"((a)[2]),"r"((a)[3]),"r"((b)[0]),"r"((b)[1]))

static __device__ __forceinline__ unsigned short bfh(float v) {
    __nv_bfloat16 h = __float2bfloat16(v);
    return *(unsigned short*)&h;
}
static __device__ __forceinline__ float bf2f(unsigned short s) {
    __nv_bfloat16 h = *(__nv_bfloat16*)&s;
    return __bfloat162float(h);
}
static __device__ __forceinline__ void split2(float v, unsigned short* o) {
    unsigned short h = bfh(v);
    o[0] = h; o[1] = bfh(v - bf2f(h));
}

#define APL 10240
#define BPL 8704
#define K4_SMEM (4*APL + 2*BPL)
#define K5_SMEM (4*APL + 4*BPL)

// ---- k1 (FFMA2, K-chunk 32): E[b,e,k,d,n] = sum_c emb*x --------------------
__global__ void __launch_bounds__(256, 2)
k1_embed(const float* __restrict__ embr, const float* __restrict__ embi,
         const float* __restrict__ xr,   const float* __restrict__ xi,
         const float* __restrict__ softr,const float* __restrict__ softi)
{
    extern __shared__ float sh[];
    float* As_r = sh + AR_O; float* As_i = sh + AI_O;
    float* Bs_r = sh + BR_O; float* Bs_i = sh + BI_O;
    int z = blockIdx.z;
    int b = z / 12, r12 = z % 12, e = r12 / KH, k = r12 % KH;
    const float* Ar_ = embr + (size_t)(e*KH + k)*Dd*Cd;
    const float* Ai_ = embi + (size_t)(e*KH + k)*Dd*Cd;
    const float* Br_ = xr + (size_t)(b*KH + k)*Cd*Nn;
    const float* Bi_ = xi + (size_t)(b*KH + k)*Cd*Nn;
    int m0 = blockIdx.y*MT, n0 = blockIdx.x*NT;
    int tid = threadIdx.x, tx = tid & 15, ty = tid >> 4;
    u64 crp[4][4] = {}, cip[4][4] = {};
    for (int c0 = 0; c0 < Cd; c0 += KT2) {
        #pragma unroll
        for (int it = 0; it < 4; it++) {
            int g = tid + it*256, m = g >> 3, kc = (g & 7)*4;
            float4 a4 = *(const float4*)&Ar_[(size_t)(m0+m)*Cd + c0 + kc];
            As_r[(kc+0)*132+m]=a4.x; As_r[(kc+1)*132+m]=a4.y;
            As_r[(kc+2)*132+m]=a4.z; As_r[(kc+3)*132+m]=a4.w;
            float4 b4 = *(const float4*)&Ai_[(size_t)(m0+m)*Cd + c0 + kc];
            As_i[(kc+0)*132+m]=b4.x; As_i[(kc+1)*132+m]=b4.y;
            As_i[(kc+2)*132+m]=b4.z; As_i[(kc+3)*132+m]=b4.w;
        }
        #pragma unroll
        for (int it = 0; it < 2; it++) {
            int g = tid + it*256, kk = g >> 4, nc = (g & 15)*4;
            *(float4*)&Bs_r[kk*64+nc] = *(const float4*)&Br_[(size_t)(c0+kk)*Nn + n0 + nc];
            *(float4*)&Bs_i[kk*64+nc] = *(const float4*)&Bi_[(size_t)(c0+kk)*Nn + n0 + nc];
        }
        __syncthreads();
        #pragma unroll 16
        for (int kk = 0; kk < KT2; kk++) {
            F4U ar0, ar1, ai0, ai1;
            ar0.f = *(const float4*)&As_r[kk*132 + ty*8];
            ar1.f = *(const float4*)&As_r[kk*132 + ty*8+4];
            ai0.f = *(const float4*)&As_i[kk*132 + ty*8];
            ai1.f = *(const float4*)&As_i[kk*132 + ty*8+4];
            u64 apr[4] = {ar0.u[0], ar0.u[1], ar1.u[0], ar1.u[1]};
            u64 api[4] = {ai0.u[0], ai0.u[1], ai1.u[0], ai1.u[1]};
            float4 brv = *(const float4*)&Bs_r[kk*64 + tx*4];
            float4 biv = *(const float4*)&Bs_i[kk*64 + tx*4];
            float brs[4] = {brv.x,brv.y,brv.z,brv.w};
            float bis[4] = {biv.x,biv.y,biv.z,biv.w};
            #pragma unroll
            for (int j = 0; j < 4; j++) {
                u64 bpr, bpi, bpn;
                PK2(bpr, brs[j]); PK2(bpi, bis[j]);
                float nb = -bis[j]; PK2(bpn, nb);
                #pragma unroll
                for (int mi = 0; mi < 4; mi++) {
                    FMA2(crp[mi][j], apr[mi], bpr);
                    FMA2(crp[mi][j], api[mi], bpn);
                    FMA2(cip[mi][j], apr[mi], bpi);
                    FMA2(cip[mi][j], api[mi], bpr);
                }
            }
        }
        __syncthreads();
    }
    float* Eor = g_Er + ((size_t)(b*3 + e)*KH + k)*Dd*Nn;
    float* Eoi = g_Ei + ((size_t)(b*3 + e)*KH + k)*Dd*Nn;
    #pragma unroll
    for (int r = 0; r < 8; r++) {
        int m = m0 + ty*8 + r, mi = r >> 1, hi = r & 1;
        float sr = 1.f, si = 0.f;
        if (e == 1) { int h = m >> 6; sr = softr[k*NHh+h]; si = softi[k*NHh+h]; }
        float vr[4], vi[4];
        #pragma unroll
        for (int j = 0; j < 4; j++) {
            float2 c2r = unp2(crp[mi][j]), c2i = unp2(cip[mi][j]);
            float cr = hi ? c2r.y : c2r.x, ci = hi ? c2i.y : c2i.x;
            vr[j] = cr*sr - ci*si; vi[j] = cr*si + ci*sr;
        }
        *(float4*)&Eor[(size_t)m*Nn + n0 + tx*4] = make_float4(vr[0],vr[1],vr[2],vr[3]);
        *(float4*)&Eoi[(size_t)m*Nn + n0 + tx*4] = make_float4(vi[0],vi[1],vi[2],vi[3]);
    }
}

// ---- kP (all b) --------------------------------------------------------------
__global__ void kP_pos(const float* __restrict__ encr, const float* __restrict__ enci,
                       const float* __restrict__ softr,const float* __restrict__ softi,
                       int n_encr, int n_enci, int n_softr, int n_softi)
{
    int y = blockIdx.y;
    int b = y / (KH*NHh), k = (y / NHh) % KH, h = y % NHh;
    int i = blockIdx.x*256 + threadIdx.x;
    size_t e0 = (size_t)(b*3)*KH*Dd*Nn + (size_t)(k*Dd + h*QDq)*Nn;
    const float* E0r = g_Er + e0;
    const float* E0i = g_Ei + e0;
    float accr = 0.f, acci = 0.f;
    for (int q = 0; q < QDq; q++) {
        float er = E0r[(size_t)q*Nn + i], ei = E0i[(size_t)q*Nn + i];
        float nr = ldin(encr, (k*NHh + h)*QDq + q, n_encr);
        float ni = ldin(enci, (k*NHh + h)*QDq + q, n_enci);
        accr += er*nr + ei*ni;
        acci += er*ni - ei*nr;
    }
    float sr = ldin(softr, k*NHh + h, n_softr);
    float si = ldin(softi, k*NHh + h, n_softi);
    float tr = accr*sr - acci*si, ti = accr*si + acci*sr;
    float s, c;
    sincosf(THETAF * (float)(k*i), &s, &c);
    int o = ((b*KH + k)*NHh + h)*Nn + i;
    g_Pr[o] = tr*c - ti*s;
    g_Pi[o] = tr*s + ti*c;
}

// ---- k2 (FFMA2, K-chunk 32): S = |GEMM + pos| / 8 ----------------------------
__global__ void __launch_bounds__(256, 2) k2_scores()
{
    extern __shared__ float sh[];
    float* As_r = sh + AR_O; float* As_i = sh + AI_O;
    float* Bs_r = sh + BR_O; float* Bs_i = sh + BI_O;
    int z = blockIdx.z;
    int b = z >> 3, h = z & 7;
    int i0 = blockIdx.y*MT, j0 = blockIdx.x*NT;
    int tid = threadIdx.x, tx = tid & 15, ty = tid >> 4;
    const float* E1r = g_Er + (size_t)(b*3 + 1)*KH*Dd*Nn;
    const float* E1i = g_Ei + (size_t)(b*3 + 1)*KH*Dd*Nn;
    const float* E0r = g_Er + (size_t)(b*3)*KH*Dd*Nn;
    const float* E0i = g_Ei + (size_t)(b*3)*KH*Dd*Nn;
    u64 crp[4][4] = {}, cip[4][4] = {};
    for (int l0 = 0; l0 < KH*QDq; l0 += KT2) {
        #pragma unroll
        for (int it = 0; it < 4; it++) {
            int g = tid + it*256, lk = g >> 5, ic = (g & 31)*4;
            int l = l0 + lk, kq = l >> 6, q = l & 63;
            size_t ro = (size_t)(kq*Dd + h*QDq + q)*Nn;
            *(float4*)&As_r[lk*132 + ic] = *(const float4*)&E1r[ro + i0 + ic];
            *(float4*)&As_i[lk*132 + ic] = *(const float4*)&E1i[ro + i0 + ic];
        }
        #pragma unroll
        for (int it = 0; it < 2; it++) {
            int g = tid + it*256, kk = g >> 4, nc = (g & 15)*4;
            int l = l0 + kk, kq = l >> 6, q = l & 63;
            size_t ro = (size_t)(kq*Dd + h*QDq + q)*Nn;
            *(float4*)&Bs_r[kk*64 + nc] = *(const float4*)&E0r[ro + j0 + nc];
            float4 c4 = *(const float4*)&E0i[ro + j0 + nc];
            *(float4*)&Bs_i[kk*64 + nc] = make_float4(-c4.x,-c4.y,-c4.z,-c4.w);
        }
        __syncthreads();
        #pragma unroll 16
        for (int kk = 0; kk < KT2; kk++) {
            F4U ar0, ar1, ai0, ai1;
            ar0.f = *(const float4*)&As_r[kk*132 + ty*8];
            ar1.f = *(const float4*)&As_r[kk*132 + ty*8+4];
            ai0.f = *(const float4*)&As_i[kk*132 + ty*8];
            ai1.f = *(const float4*)&As_i[kk*132 + ty*8+4];
            u64 apr[4] = {ar0.u[0], ar0.u[1], ar1.u[0], ar1.u[1]};
            u64 api[4] = {ai0.u[0], ai0.u[1], ai1.u[0], ai1.u[1]};
            float4 brv = *(const float4*)&Bs_r[kk*64 + tx*4];
            float4 biv = *(const float4*)&Bs_i[kk*64 + tx*4];
            float brs[4] = {brv.x,brv.y,brv.z,brv.w};
            float bis[4] = {biv.x,biv.y,biv.z,biv.w};
            #pragma unroll
            for (int j = 0; j < 4; j++) {
                u64 bpr, bpi, bpn;
                PK2(bpr, brs[j]); PK2(bpi, bis[j]);
                float nb = -bis[j]; PK2(bpn, nb);
                #pragma unroll
                for (int mi = 0; mi < 4; mi++) {
                    FMA2(crp[mi][j], apr[mi], bpr);
                    FMA2(crp[mi][j], api[mi], bpn);
                    FMA2(cip[mi][j], apr[mi], bpi);
                    FMA2(cip[mi][j], api[mi], bpr);
                }
            }
        }
        __syncthreads();
    }
    #pragma unroll
    for (int j = 0; j < 4; j++) {
        int jj = j0 + tx*4 + j;
        float s, c;
        sincosf(-THETAF * (float)jj, &s, &c);
        float wr = c, wi = s, curr = 1.f, curi = 0.f;
        #pragma unroll
        for (int kq = 0; kq < KH; kq++) {
            u64 cp, sp, sn;
            PK2(cp, curr); PK2(sp, curi);
            float ns = -curi; PK2(sn, ns);
            #pragma unroll
            for (int mi = 0; mi < 4; mi++) {
                int i = i0 + ty*8 + mi*2;
                int off = ((b*KH + kq)*NHh + h)*Nn + i;
                u64 ppr = *(const u64*)&g_Pr[off];
                u64 ppi = *(const u64*)&g_Pi[off];
                FMA2(crp[mi][j], ppr, cp);
                FMA2(crp[mi][j], ppi, sn);
                FMA2(cip[mi][j], ppr, sp);
                FMA2(cip[mi][j], ppi, cp);
            }
            float nr = curr*wr - curi*wi;
            curi = curr*wi + curi*wr;
            curr = nr;
        }
    }
    float* So = g_S + (size_t)(b*NHh + h)*Nn*Nn;
    #pragma unroll
    for (int r = 0; r < 8; r++) {
        int i = i0 + ty*8 + r, mi = r >> 1, hi = r & 1;
        float sv[4];
        #pragma unroll
        for (int j = 0; j < 4; j++) {
            float2 c2r = unp2(crp[mi][j]), c2i = unp2(cip[mi][j]);
            float cr = hi ? c2r.y : c2r.x, ci = hi ? c2i.y : c2i.x;
            sv[j] = sqrtf(cr*cr + ci*ci) * 0.125f;
        }
        *(float4*)&So[(size_t)i*Nn + j0 + tx*4] = make_float4(sv[0],sv[1],sv[2],sv[3]);
    }
}

// ---- k3 (2-pass): exp in place; 1/sum -> g_inv (normalize folded into k4) --
__global__ void k3_softmax()
{
    __shared__ __align__(16) float red[8][33];
    int y = blockIdx.y;
    int b = y >> 3, h = y & 7;
    int tx = threadIdx.x, ty = threadIdx.y;
    int j = blockIdx.x*32 + tx;
    size_t base = (size_t)(b*NHh + h)*Nn*Nn;
    float mx = -1e30f;
    for (int i = ty; i < Nn; i += 8)
        mx = fmaxf(mx, g_S[base + (size_t)i*Nn + j]);
    red[ty][tx] = mx;
    __syncthreads();
    if (ty == 0) {
        float m = red[0][tx];
        #pragma unroll
        for (int r = 1; r < 8; r++) m = fmaxf(m, red[r][tx]);
        red[0][tx] = m;
    }
    __syncthreads();
    mx = red[0][tx];
    __syncthreads();
    float sum = 0.f;
    for (int i = ty; i < Nn; i += 8) {
        size_t o = base + (size_t)i*Nn + j;
        float e = expf(g_S[o] - mx);
        g_S[o] = e;
        sum += e;
    }
    red[ty][tx] = sum;
    __syncthreads();
    if (ty == 0) {
        float s = red[0][tx];
        #pragma unroll
        for (int r = 1; r < 8; r++) s += red[r][tx];
        g_inv[(b*NHh + h)*Nn + j] = 1.0f / s;
    }
}

// ---- k4 (mma 2-split, normalize-on-load): ctx = V @ (S*inv) ----------------
__global__ void __launch_bounds__(512, 1) k4_mma()
{
    extern __shared__ char sm[];
    u32 smA = smem_u32(sm);
    u32 smB = smA + 4*APL;
    int tid = threadIdx.x, wid = tid >> 5, lane = tid & 31;
    int wm = wid >> 2, wn = wid & 3;
    int z = blockIdx.z, b = z >> 3, h = z & 7;
    int m0 = blockIdx.y*128, j0 = blockIdx.x*128;
    const float* Vr = g_Er + (size_t)(b*3 + 2)*KH*Dd*Nn;
    const float* Vi = g_Ei + (size_t)(b*3 + 2)*KH*Dd*Nn;
    const float* S  = g_S + (size_t)(b*NHh + h)*Nn*Nn;
    const float* inv = g_inv + (b*NHh + h)*Nn;
    const int PA2[3] = {0, 0, 1};
    const int PB2[3] = {0, 1, 0};
    float dr[2][4][4] = {}, di[2][4][4] = {};
    u32 aRowOff = (u32)((wm*32 + (lane & 15))*80 + (lane >> 4)*16);
    u32 bColOff = (u32)(wn*64);

    for (int c0 = 0; c0 < Nn; c0 += 32) {
        #pragma unroll
        for (int it = 0; it < 2; it++) {
            int t = tid + it*512;
            int m = t >> 3, c4 = (t & 7)*4;
            int l = m0 + m, kq = l >> 6, q = l & 63;
            size_t ro = (size_t)(kq*Dd + h*QDq + q)*Nn;
            float4 vr = *(const float4*)&Vr[ro + c0 + c4];
            float4 vi = *(const float4*)&Vi[ro + c0 + c4];
            unsigned short hh[4], ll[4], s2[2];
            u32 wo = (u32)(m*80 + c4*2);
            float rs[4] = {vr.x, vr.y, vr.z, vr.w};
            #pragma unroll
            for (int j = 0; j < 4; j++) { split2(rs[j], s2); hh[j]=s2[0]; ll[j]=s2[1]; }
            *(u64*)(sm + 0*APL + wo) = (u64)hh[0] | ((u64)hh[1]<<16) | ((u64)hh[2]<<32) | ((u64)hh[3]<<48);
            *(u64*)(sm + 1*APL + wo) = (u64)ll[0] | ((u64)ll[1]<<16) | ((u64)ll[2]<<32) | ((u64)ll[3]<<48);
            float is[4] = {vi.x, vi.y, vi.z, vi.w};
            #pragma unroll
            for (int j = 0; j < 4; j++) { split2(is[j], s2); hh[j]=s2[0]; ll[j]=s2[1]; }
            *(u64*)(sm + 2*APL + wo) = (u64)hh[0] | ((u64)hh[1]<<16) | ((u64)hh[2]<<32) | ((u64)hh[3]<<48);
            *(u64*)(sm + 3*APL + wo) = (u64)ll[0] | ((u64)ll[1]<<16) | ((u64)ll[2]<<32) | ((u64)ll[3]<<48);
        }
        #pragma unroll
        for (int it = 0; it < 2; it++) {
            int t = tid + it*512;
            int c = t >> 5, n4 = (t & 31)*4;
            float4 sv = *(const float4*)&S[(size_t)(c0 + c)*Nn + j0 + n4];
            float4 iv = *(const float4*)&inv[j0 + n4];
            unsigned short hh[4], ll[4], s2[2];
            u32 wo = (u32)(c*272 + n4*2);
            float ss[4] = {sv.x*iv.x, sv.y*iv.y, sv.z*iv.z, sv.w*iv.w};
            #pragma unroll
            for (int j = 0; j < 4; j++) { split2(ss[j], s2); hh[j]=s2[0]; ll[j]=s2[1]; }
            char* bb = sm + 4*APL;
            *(u64*)(bb + 0*BPL + wo) = (u64)hh[0] | ((u64)hh[1]<<16) | ((u64)hh[2]<<32) | ((u64)hh[3]<<48);
            *(u64*)(bb + 1*BPL + wo) = (u64)ll[0] | ((u64)ll[1]<<16) | ((u64)ll[2]<<32) | ((u64)ll[3]<<48);
        }
        __syncthreads();
        #pragma unroll
        for (int ks = 0; ks < 2; ks++) {
            #pragma unroll
            for (int s = 0; s < 3; s++) {
                u32 ar0[4], ar1[4], ai0[4], ai1[4];
                u32 abase = smA + aRowOff + (u32)(ks*32);
                LDSM4(ar0, abase + PA2[s]*APL);
                LDSM4(ar1, abase + PA2[s]*APL + 16*80);
                LDSM4(ai0, abase + (2+PA2[s])*APL);
                LDSM4(ai1, abase + (2+PA2[s])*APL + 16*80);
                u32 bbase = smB + (u32)((ks*16 + (lane & 15))*272) + bColOff;
                #pragma unroll
                for (int nt = 0; nt < 4; nt++) {
                    u32 bb[2];
                    LDSM2T(bb, bbase + (u32)(nt*16) + PB2[s]*BPL);
                    MMABF(dr[0][nt], ar0, bb); MMABF(di[0][nt], ai0, bb);
                    MMABF(dr[1][nt], ar1, bb); MMABF(di[1][nt], ai1, bb);
                }
            }
        }
        __syncthreads();
    }
    size_t cb = (size_t)b*KH*Cd*Nn;
    #pragma unroll
    for (int mt = 0; mt < 2; mt++) {
        #pragma unroll
        for (int ch = 0; ch < 2; ch++) {
            int l = m0 + wm*32 + mt*16 + (lane >> 2) + ch*8;
            int kq = l >> 6, q = l & 63;
            size_t ro = cb + (size_t)(kq*Cd + h*QDq + q)*Nn;
            #pragma unroll
            for (int nt = 0; nt < 4; nt++) {
                int j = j0 + wn*32 + nt*8 + (lane & 3)*2;
                *(float2*)&g_ctxr[ro + j] = make_float2(dr[mt][nt][ch*2], dr[mt][nt][ch*2+1]);
                *(float2*)&g_ctxi[ro + j] = make_float2(di[mt][nt][ch*2], di[mt][nt][ch*2+1]);
            }
        }
    }
}

// ---- k5 (mma 2-split, real-only): res = Re(out @ ctx) ------------------------
__global__ void __launch_bounds__(512, 1)
k5_mma(const float* __restrict__ outr, const float* __restrict__ outi,
       float* __restrict__ res, int n_res)
{
    extern __shared__ char sm[];
    u32 smA = smem_u32(sm);
    u32 smB = smA + 4*APL;
    int tid = threadIdx.x, wid = tid >> 5, lane = tid & 31;
    int wm = wid >> 2, wn = wid & 3;
    int z = blockIdx.z, b = z >> 2, k = z & 3;
    int m0 = blockIdx.y*128, j0 = blockIdx.x*128;
    const float* Ar = outr + (size_t)k*Dd*Cd;
    const float* Ai = outi + (size_t)k*Dd*Cd;
    const float* Br = g_ctxr + ((size_t)b*KH + k)*Cd*Nn;
    const float* Bi = g_ctxi + ((size_t)b*KH + k)*Cd*Nn;
    const int PA2[3] = {0, 0, 1};
    const int PB2[3] = {0, 1, 0};
    float dr[2][4][4] = {};
    u32 aRowOff = (u32)((wm*32 + (lane & 15))*80 + (lane >> 4)*16);
    u32 bColOff = (u32)(wn*64);

    for (int c0 = 0; c0 < Cd; c0 += 32) {
        #pragma unroll
        for (int it = 0; it < 2; it++) {
            int t = tid + it*512;
            int m = t >> 3, c4 = (t & 7)*4;
            float4 vr = *(const float4*)&Ar[(size_t)(m0+m)*Cd + c0 + c4];
            float4 vi = *(const float4*)&Ai[(size_t)(m0+m)*Cd + c0 + c4];
            unsigned short hh[4], ll[4], s2[2];
            u32 wo = (u32)(m*80 + c4*2);
            float rs[4] = {vr.x, vr.y, vr.z, vr.w};
            #pragma unroll
            for (int j = 0; j < 4; j++) { split2(rs[j], s2); hh[j]=s2[0]; ll[j]=s2[1]; }
            *(u64*)(sm + 0*APL + wo) = (u64)hh[0] | ((u64)hh[1]<<16) | ((u64)hh[2]<<32) | ((u64)hh[3]<<48);
            *(u64*)(sm + 1*APL + wo) = (u64)ll[0] | ((u64)ll[1]<<16) | ((u64)ll[2]<<32) | ((u64)ll[3]<<48);
            float is[4] = {-vi.x, -vi.y, -vi.z, -vi.w};
            #pragma unroll
            for (int j = 0; j < 4; j++) { split2(is[j], s2); hh[j]=s2[0]; ll[j]=s2[1]; }
            *(u64*)(sm + 2*APL + wo) = (u64)hh[0] | ((u64)hh[1]<<16) | ((u64)hh[2]<<32) | ((u64)hh[3]<<48);
            *(u64*)(sm + 3*APL + wo) = (u64)ll[0] | ((u64)ll[1]<<16) | ((u64)ll[2]<<32) | ((u64)ll[3]<<48);
        }
        #pragma unroll
        for (int it = 0; it < 2; it++) {
            int t = tid + it*512;
            int c = t >> 5, n4 = (t & 31)*4;
            size_t go = (size_t)(c0 + c)*Nn + j0 + n4;
            float4 vr = *(const float4*)&Br[go];
            float4 vi = *(const float4*)&Bi[go];
            unsigned short hh[4], ll[4], s2[2];
            u32 wo = (u32)(c*272 + n4*2);
            char* bb = sm + 4*APL;
            float rs[4] = {vr.x, vr.y, vr.z, vr.w};
            #pragma unroll
            for (int j = 0; j < 4; j++) { split2(rs[j], s2); hh[j]=s2[0]; ll[j]=s2[1]; }
            *(u64*)(bb + 0*BPL + wo) = (u64)hh[0] | ((u64)hh[1]<<16) | ((u64)hh[2]<<32) | ((u64)hh[3]<<48);
            *(u64*)(bb + 1*BPL + wo) = (u64)ll[0] | ((u64)ll[1]<<16) | ((u64)ll[2]<<32) | ((u64)ll[3]<<48);
            float is[4] = {vi.x, vi.y, vi.z, vi.w};
            #pragma unroll
            for (int j = 0; j < 4; j++) { split2(is[j], s2); hh[j]=s2[0]; ll[j]=s2[1]; }
            *(u64*)(bb + 2*BPL + wo) = (u64)hh[0] | ((u64)hh[1]<<16) | ((u64)hh[2]<<32) | ((u64)hh[3]<<48);
            *(u64*)(bb + 3*BPL + wo) = (u64)ll[0] | ((u64)ll[1]<<16) | ((u64)ll[2]<<32) | ((u64)ll[3]<<48);
        }
        __syncthreads();
        #pragma unroll
        for (int ks = 0; ks < 2; ks++) {
            #pragma unroll
            for (int s = 0; s < 3; s++) {
                u32 ar0[4], ar1[4], an0[4], an1[4];
                u32 abase = smA + aRowOff + (u32)(ks*32);
                LDSM4(ar0, abase + PA2[s]*APL);
                LDSM4(ar1, abase + PA2[s]*APL + 16*80);
                LDSM4(an0, abase + (2+PA2[s])*APL);
                LDSM4(an1, abase + (2+PA2[s])*APL + 16*80);
                u32 bbase = smB + (u32)((ks*16 + (lane & 15))*272) + bColOff;
                #pragma unroll
                for (int nt = 0; nt < 4; nt++) {
                    u32 br[2], bi2[2];
                    u32 boff = bbase + (u32)(nt*16);
                    LDSM2T(br, boff + PB2[s]*BPL);
                    LDSM2T(bi2, boff + (2+PB2[s])*BPL);
                    MMABF(dr[0][nt], ar0, br); MMABF(dr[0][nt], an0, bi2);
                    MMABF(dr[1][nt], ar1, br); MMABF(dr[1][nt], an1, bi2);
                }
            }
        }
        __syncthreads();
    }
    int nlim = n_res < OUT_ELEMS ? n_res : OUT_ELEMS;
    #pragma unroll
    for (int mt = 0; mt < 2; mt++) {
        #pragma unroll
        for (int ch = 0; ch < 2; ch++) {
            int d = m0 + wm*32 + mt*16 + (lane >> 2) + ch*8;
            size_t row = ((size_t)(b*KH + k)*Dd + d)*Nn;
            #pragma unroll
            for (int nt = 0; nt < 4; nt++) {
                int j = j0 + wn*32 + nt*8 + (lane & 3)*2;
                size_t o = row + j;
                float v0 = dr[mt][nt][ch*2], v1 = dr[mt][nt][ch*2+1];
                if (o + 2 <= (size_t)nlim) {
                    *(float2*)&res[o] = make_float2(v0, v1);
                } else {
                    if (o < (size_t)nlim) res[o] = v0;
                    if (o + 1 < (size_t)nlim) res[o+1] = v1;
                }
            }
        }
    }
}

// ---------------- launch -----------------------------------------------------
static int classify_sz(int sz, int* elems) {
    switch (sz) {
        case 8388608:  *elems = sz;   return 0;
        case 33554432: *elems = sz/4; return 0;
        case 3145728:  *elems = sz;   return 1;
        case 12582912: *elems = sz/4; return 1;
        case 2048:     *elems = sz;   return 2;
        case 8192:     *elems = sz/4; return 2;
        case 32:       *elems = sz;   return 3;
        case 128:      *elems = sz/4; return 3;
        case 1048576:  *elems = sz;   return 4;
        case 4194304:  *elems = sz/4; return 4;
        default: *elems = 0; return -1;
    }
}

extern "C" void kernel_launch(void* const* d_in, const int* in_sizes, int n_in,
                              void* d_out, int out_size)
{
    const float* pairs[5][2] = {};
    int psz[5][2] = {};
    int cnt[5] = {};
    bool ok = (n_in == 10) && d_out;
    if (ok) for (int i = 0; i < n_in; i++) if (!d_in[i]) ok = false;

    if (ok) {
        for (int i = 0; i < n_in; i++) {
            int el; int c = classify_sz(in_sizes[i], &el);
            if (c < 0 || cnt[c] >= 2) { ok = false; break; }
            pairs[c][cnt[c]] = (const float*)d_in[i];
            psz[c][cnt[c]] = el;
            cnt[c]++;
        }
        if (ok) for (int c = 0; c < 5; c++) if (cnt[c] != 2) ok = false;
    }

    const float *xr, *xi, *embr, *embi, *encr, *enci, *softr, *softi, *outr, *outi;
    int nencr, nenci, nsoftr, nsofti;
    if (ok) {
        int el0; int c0 = classify_sz(in_sizes[0], &el0);
        int ri = (c0 == 1) ? 1 : 0;
        int im = 1 - ri;
        xr    = pairs[0][ri]; xi    = pairs[0][im];
        embr  = pairs[1][ri]; embi  = pairs[1][im];
        encr  = pairs[2][ri]; nencr  = psz[2][ri]; enci  = pairs[2][im]; nenci  = psz[2][im];
        softr = pairs[3][ri]; nsoftr = psz[3][ri]; softi = pairs[3][im]; nsofti = psz[3][im];
        outr  = pairs[4][ri]; outi  = pairs[4][im];
    } else if (n_in >= 10 && d_out) {
        xr    = (const float*)d_in[0]; xi    = (const float*)d_in[1];
        embr  = (const float*)d_in[2]; embi  = (const float*)d_in[3];
        encr  = (const float*)d_in[4]; nencr  = in_sizes[4];
        enci  = (const float*)d_in[5]; nenci  = in_sizes[5];
        softr = (const float*)d_in[6]; nsoftr = in_sizes[6];
        softi = (const float*)d_in[7]; nsofti = in_sizes[7];
        outr  = (const float*)d_in[8]; outi  = (const float*)d_in[9];
    } else {
        return;
    }

    cudaFuncSetAttribute(k1_embed, cudaFuncAttributeMaxDynamicSharedMemorySize, K12_SMEM);
    cudaFuncSetAttribute(k2_scores, cudaFuncAttributeMaxDynamicSharedMemorySize, K12_SMEM);
    cudaFuncSetAttribute(k4_mma, cudaFuncAttributeMaxDynamicSharedMemorySize, K4_SMEM);
    cudaFuncSetAttribute(k5_mma, cudaFuncAttributeMaxDynamicSharedMemorySize, K5_SMEM);

    k1_embed<<<dim3(Nn/NT, Dd/MT, 12*Bn), 256, K12_SMEM>>>(embr, embi, xr, xi, softr, softi);
    kP_pos<<<dim3(Nn/256, Bn*KH*NHh), 256>>>(encr, enci, softr, softi,
                                             nencr, nenci, nsoftr, nsofti);
    k2_scores<<<dim3(Nn/NT, Nn/MT, Bn*NHh), 256, K12_SMEM>>>();
    k3_softmax<<<dim3(Nn/32, Bn*NHh), dim3(32, 8)>>>();
    k4_mma<<<dim3(Nn/128, (KH*QDq)/128, Bn*NHh), 512, K4_SMEM>>>();
    k5_mma<<<dim3(Nn/128, Dd/128, Bn*KH), 512, K5_SMEM>>>(outr, outi,
                                                          (float*)d_out, out_size);
}

// round 15
// speedup vs baseline: 1.0463x; 1.0159x over previous
#include <cuda_runtime.h>
#include <cuda_bf16.h>
#include <math.h>

#define Bn 4
#define KH 4
#define Cd 512
#define Dd 512
#define Nn 1024
#define NHh 8
#define QDq 64
#define THETAF (6.2831853071795865f / 1024.0f)
#define OUT_ELEMS 8388608

#define MT 128
#define NT 64
#define KT2 32

#define AR_O 0
#define AI_O 4224
#define BR_O 8448
#define BI_O 10496
#define K12_SMEM 50176

// ---------------- scratch ----------------------------------------------------
__device__ float g_Er[(size_t)Bn*3*KH*Dd*Nn];
__device__ float g_Ei[(size_t)Bn*3*KH*Dd*Nn];
__device__ float g_S [(size_t)Bn*NHh*Nn*Nn];
__device__ float g_Pr[Bn*KH*NHh*Nn];
__device__ float g_Pi[Bn*KH*NHh*Nn];
__device__ float g_inv[Bn*NHh*Nn];
// bf16 2-split planes
__device__ unsigned short g_Vrh[(size_t)Bn*KH*Dd*Nn], g_Vrl[(size_t)Bn*KH*Dd*Nn];
__device__ unsigned short g_Vih[(size_t)Bn*KH*Dd*Nn], g_Vil[(size_t)Bn*KH*Dd*Nn];
__device__ unsigned short g_Crh[(size_t)Bn*KH*Cd*Nn], g_Crl[(size_t)Bn*KH*Cd*Nn];
__device__ unsigned short g_Cih[(size_t)Bn*KH*Cd*Nn], g_Cil[(size_t)Bn*KH*Cd*Nn];
__device__ unsigned short g_Orh[KH*Dd*Cd], g_Orl[KH*Dd*Cd];
__device__ unsigned short g_Onih[KH*Dd*Cd], g_Onil[KH*Dd*Cd];

typedef unsigned long long u64;
typedef unsigned int u32;
union F4U { float4 f; u64 u[2]; };

#define PK2(d, x) asm("mov.b64 %0, {%1, %1};" : "=l"(d) : "f"(x))
#define FMA2(d, a, b) asm("fma.rn.f32x2 %0, %1, %2, %0;" : "+l"(d) : "l"(a), "l"(b))

static __device__ __forceinline__ float2 unp2(u64 v) {
    float2 r; asm("mov.b64 {%0, %1}, %2;" : "=f"(r.x), "=f"(r.y) : "l"(v)); return r;
}
static __device__ __forceinline__ float ldin(const float* p, int off, int n) {
    return (off >= 0 && off < n) ? p[off] : 0.0f;
}
static __device__ __forceinline__ u32 smem_u32(const void* p) {
    u32 a; asm("{ .reg .u64 t; cvta.to.shared.u64 t, %1; cvt.u32.u64 %0, t; }"
               : "=r"(a) : "l"(p));
    return a;
}

#define LDSM4(r, a) asm volatile( \
    "ldmatrix.sync.aligned.m8n8.x4.shared.b16 {%0,%1,%2,%3}, [%4];" \
    : "=r"((r)[0]),"=r"((r)[1]),"=r"((r)[2]),"=r"((r)[3]) : "r"(a))
#define LDSM2T(r, a) asm volatile( \
    "ldmatrix.sync.aligned.m8n8.x2.trans.shared.b16 {%0,%1}, [%2];" \
    : "=r"((r)[0]),"=r"((r)[1]) : "r"(a))
#define MMABF(d, a, b) asm volatile( \
    "mma.sync.aligned.m16n8k16.row.col.f32.bf16.bf16.f32 " \
    "{%0,%1,%2,%3},{%4,%5,%6,%7},{%8,%9},{%0,%1,%2,%3};" \
    : "+f"((d)[0]),"+f"((d)[1]),"+f"((d)[2]),"+f"((d)[3]) \
    : "r"((a)[0]),"r"((a)[1]),"r"((a)[2]),"r"((a)[3]),"r"((b)[0]),"r"((b)[1]))

static __device__ __forceinline__ unsigned short bfh(float v) {
    __nv_bfloat16 h = __float2bfloat16(v);
    return *(unsigned short*)&h;
}
static __device__ __forceinline__ float bf2f(unsigned short s) {
    __nv_bfloat16 h = *(__nv_bfloat16*)&s;
    return __bfloat162float(h);
}
static __device__ __forceinline__ void split2(float v, unsigned short* o) {
    unsigned short h = bfh(v);
    o[0] = h; o[1] = bfh(v - bf2f(h));
}

#define APL 10240
#define BPL 8704
#define K4_SMEM (4*APL + 2*BPL)
#define K5_SMEM (4*APL + 4*BPL)

// ---- kSplitOut: pre-split `out` (imag negated) into bf16 planes -------------
__global__ void kSplitOut(const float* __restrict__ outr, const float* __restrict__ outi)
{
    int i = blockIdx.x*256 + threadIdx.x;
    if (i < KH*Dd*Cd) {
        unsigned short s2[2];
        split2(outr[i], s2);  g_Orh[i] = s2[0];  g_Orl[i] = s2[1];
        split2(-outi[i], s2); g_Onih[i] = s2[0]; g_Onil[i] = s2[1];
    }
}

// ---- k1 (FFMA2, K-chunk 32): E = emb @ x; e==2 also emits bf16 V planes ----
__global__ void __launch_bounds__(256, 2)
k1_embed(const float* __restrict__ embr, const float* __restrict__ embi,
         const float* __restrict__ xr,   const float* __restrict__ xi,
         const float* __restrict__ softr,const float* __restrict__ softi)
{
    extern __shared__ float sh[];
    float* As_r = sh + AR_O; float* As_i = sh + AI_O;
    float* Bs_r = sh + BR_O; float* Bs_i = sh + BI_O;
    int z = blockIdx.z;
    int b = z / 12, r12 = z % 12, e = r12 / KH, k = r12 % KH;
    const float* Ar_ = embr + (size_t)(e*KH + k)*Dd*Cd;
    const float* Ai_ = embi + (size_t)(e*KH + k)*Dd*Cd;
    const float* Br_ = xr + (size_t)(b*KH + k)*Cd*Nn;
    const float* Bi_ = xi + (size_t)(b*KH + k)*Cd*Nn;
    int m0 = blockIdx.y*MT, n0 = blockIdx.x*NT;
    int tid = threadIdx.x, tx = tid & 15, ty = tid >> 4;
    u64 crp[4][4] = {}, cip[4][4] = {};
    for (int c0 = 0; c0 < Cd; c0 += KT2) {
        #pragma unroll
        for (int it = 0; it < 4; it++) {
            int g = tid + it*256, m = g >> 3, kc = (g & 7)*4;
            float4 a4 = *(const float4*)&Ar_[(size_t)(m0+m)*Cd + c0 + kc];
            As_r[(kc+0)*132+m]=a4.x; As_r[(kc+1)*132+m]=a4.y;
            As_r[(kc+2)*132+m]=a4.z; As_r[(kc+3)*132+m]=a4.w;
            float4 b4 = *(const float4*)&Ai_[(size_t)(m0+m)*Cd + c0 + kc];
            As_i[(kc+0)*132+m]=b4.x; As_i[(kc+1)*132+m]=b4.y;
            As_i[(kc+2)*132+m]=b4.z; As_i[(kc+3)*132+m]=b4.w;
        }
        #pragma unroll
        for (int it = 0; it < 2; it++) {
            int g = tid + it*256, kk = g >> 4, nc = (g & 15)*4;
            *(float4*)&Bs_r[kk*64+nc] = *(const float4*)&Br_[(size_t)(c0+kk)*Nn + n0 + nc];
            *(float4*)&Bs_i[kk*64+nc] = *(const float4*)&Bi_[(size_t)(c0+kk)*Nn + n0 + nc];
        }
        __syncthreads();
        #pragma unroll 16
        for (int kk = 0; kk < KT2; kk++) {
            F4U ar0, ar1, ai0, ai1;
            ar0.f = *(const float4*)&As_r[kk*132 + ty*8];
            ar1.f = *(const float4*)&As_r[kk*132 + ty*8+4];
            ai0.f = *(const float4*)&As_i[kk*132 + ty*8];
            ai1.f = *(const float4*)&As_i[kk*132 + ty*8+4];
            u64 apr[4] = {ar0.u[0], ar0.u[1], ar1.u[0], ar1.u[1]};
            u64 api[4] = {ai0.u[0], ai0.u[1], ai1.u[0], ai1.u[1]};
            float4 brv = *(const float4*)&Bs_r[kk*64 + tx*4];
            float4 biv = *(const float4*)&Bs_i[kk*64 + tx*4];
            float brs[4] = {brv.x,brv.y,brv.z,brv.w};
            float bis[4] = {biv.x,biv.y,biv.z,biv.w};
            #pragma unroll
            for (int j = 0; j < 4; j++) {
                u64 bpr, bpi, bpn;
                PK2(bpr, brs[j]); PK2(bpi, bis[j]);
                float nb = -bis[j]; PK2(bpn, nb);
                #pragma unroll
                for (int mi = 0; mi < 4; mi++) {
                    FMA2(crp[mi][j], apr[mi], bpr);
                    FMA2(crp[mi][j], api[mi], bpn);
                    FMA2(cip[mi][j], apr[mi], bpi);
                    FMA2(cip[mi][j], api[mi], bpr);
                }
            }
        }
        __syncthreads();
    }
    float* Eor = g_Er + ((size_t)(b*3 + e)*KH + k)*Dd*Nn;
    float* Eoi = g_Ei + ((size_t)(b*3 + e)*KH + k)*Dd*Nn;
    #pragma unroll
    for (int r = 0; r < 8; r++) {
        int m = m0 + ty*8 + r, mi = r >> 1, hi = r & 1;
        float sr = 1.f, si = 0.f;
        if (e == 1) { int h = m >> 6; sr = softr[k*NHh+h]; si = softi[k*NHh+h]; }
        float vr[4], vi[4];
        #pragma unroll
        for (int j = 0; j < 4; j++) {
            float2 c2r = unp2(crp[mi][j]), c2i = unp2(cip[mi][j]);
            float cr = hi ? c2r.y : c2r.x, ci = hi ? c2i.y : c2i.x;
            vr[j] = cr*sr - ci*si; vi[j] = cr*si + ci*sr;
        }
        *(float4*)&Eor[(size_t)m*Nn + n0 + tx*4] = make_float4(vr[0],vr[1],vr[2],vr[3]);
        *(float4*)&Eoi[(size_t)m*Nn + n0 + tx*4] = make_float4(vi[0],vi[1],vi[2],vi[3]);
        if (e == 2) {
            size_t vb = ((size_t)b*KH + k)*Dd*Nn + (size_t)m*Nn + n0 + tx*4;
            unsigned short h4[4], l4[4], s2[2];
            #pragma unroll
            for (int j = 0; j < 4; j++) { split2(vr[j], s2); h4[j]=s2[0]; l4[j]=s2[1]; }
            *(u64*)&g_Vrh[vb] = (u64)h4[0] | ((u64)h4[1]<<16) | ((u64)h4[2]<<32) | ((u64)h4[3]<<48);
            *(u64*)&g_Vrl[vb] = (u64)l4[0] | ((u64)l4[1]<<16) | ((u64)l4[2]<<32) | ((u64)l4[3]<<48);
            #pragma unroll
            for (int j = 0; j < 4; j++) { split2(vi[j], s2); h4[j]=s2[0]; l4[j]=s2[1]; }
            *(u64*)&g_Vih[vb] = (u64)h4[0] | ((u64)h4[1]<<16) | ((u64)h4[2]<<32) | ((u64)h4[3]<<48);
            *(u64*)&g_Vil[vb] = (u64)l4[0] | ((u64)l4[1]<<16) | ((u64)l4[2]<<32) | ((u64)l4[3]<<48);
        }
    }
}

// ---- kP ----------------------------------------------------------------------
__global__ void kP_pos(const float* __restrict__ encr, const float* __restrict__ enci,
                       const float* __restrict__ softr,const float* __restrict__ softi,
                       int n_encr, int n_enci, int n_softr, int n_softi)
{
    int y = blockIdx.y;
    int b = y / (KH*NHh), k = (y / NHh) % KH, h = y % NHh;
    int i = blockIdx.x*256 + threadIdx.x;
    size_t e0 = (size_t)(b*3)*KH*Dd*Nn + (size_t)(k*Dd + h*QDq)*Nn;
    const float* E0r = g_Er + e0;
    const float* E0i = g_Ei + e0;
    float accr = 0.f, acci = 0.f;
    for (int q = 0; q < QDq; q++) {
        float er = E0r[(size_t)q*Nn + i], ei = E0i[(size_t)q*Nn + i];
        float nr = ldin(encr, (k*NHh + h)*QDq + q, n_encr);
        float ni = ldin(enci, (k*NHh + h)*QDq + q, n_enci);
        accr += er*nr + ei*ni;
        acci += er*ni - ei*nr;
    }
    float sr = ldin(softr, k*NHh + h, n_softr);
    float si = ldin(softi, k*NHh + h, n_softi);
    float tr = accr*sr - acci*si, ti = accr*si + acci*sr;
    float s, c;
    sincosf(THETAF * (float)(k*i), &s, &c);
    int o = ((b*KH + k)*NHh + h)*Nn + i;
    g_Pr[o] = tr*c - ti*s;
    g_Pi[o] = tr*s + ti*c;
}

// ---- k2 (FFMA2, K-chunk 32): S = |GEMM + pos| / 8 ----------------------------
__global__ void __launch_bounds__(256, 2) k2_scores()
{
    extern __shared__ float sh[];
    float* As_r = sh + AR_O; float* As_i = sh + AI_O;
    float* Bs_r = sh + BR_O; float* Bs_i = sh + BI_O;
    int z = blockIdx.z;
    int b = z >> 3, h = z & 7;
    int i0 = blockIdx.y*MT, j0 = blockIdx.x*NT;
    int tid = threadIdx.x, tx = tid & 15, ty = tid >> 4;
    const float* E1r = g_Er + (size_t)(b*3 + 1)*KH*Dd*Nn;
    const float* E1i = g_Ei + (size_t)(b*3 + 1)*KH*Dd*Nn;
    const float* E0r = g_Er + (size_t)(b*3)*KH*Dd*Nn;
    const float* E0i = g_Ei + (size_t)(b*3)*KH*Dd*Nn;
    u64 crp[4][4] = {}, cip[4][4] = {};
    for (int l0 = 0; l0 < KH*QDq; l0 += KT2) {
        #pragma unroll
        for (int it = 0; it < 4; it++) {
            int g = tid + it*256, lk = g >> 5, ic = (g & 31)*4;
            int l = l0 + lk, kq = l >> 6, q = l & 63;
            size_t ro = (size_t)(kq*Dd + h*QDq + q)*Nn;
            *(float4*)&As_r[lk*132 + ic] = *(const float4*)&E1r[ro + i0 + ic];
            *(float4*)&As_i[lk*132 + ic] = *(const float4*)&E1i[ro + i0 + ic];
        }
        #pragma unroll
        for (int it = 0; it < 2; it++) {
            int g = tid + it*256, kk = g >> 4, nc = (g & 15)*4;
            int l = l0 + kk, kq = l >> 6, q = l & 63;
            size_t ro = (size_t)(kq*Dd + h*QDq + q)*Nn;
            *(float4*)&Bs_r[kk*64 + nc] = *(const float4*)&E0r[ro + j0 + nc];
            float4 c4 = *(const float4*)&E0i[ro + j0 + nc];
            *(float4*)&Bs_i[kk*64 + nc] = make_float4(-c4.x,-c4.y,-c4.z,-c4.w);
        }
        __syncthreads();
        #pragma unroll 16
        for (int kk = 0; kk < KT2; kk++) {
            F4U ar0, ar1, ai0, ai1;
            ar0.f = *(const float4*)&As_r[kk*132 + ty*8];
            ar1.f = *(const float4*)&As_r[kk*132 + ty*8+4];
            ai0.f = *(const float4*)&As_i[kk*132 + ty*8];
            ai1.f = *(const float4*)&As_i[kk*132 + ty*8+4];
            u64 apr[4] = {ar0.u[0], ar0.u[1], ar1.u[0], ar1.u[1]};
            u64 api[4] = {ai0.u[0], ai0.u[1], ai1.u[0], ai1.u[1]};
            float4 brv = *(const float4*)&Bs_r[kk*64 + tx*4];
            float4 biv = *(const float4*)&Bs_i[kk*64 + tx*4];
            float brs[4] = {brv.x,brv.y,brv.z,brv.w};
            float bis[4] = {biv.x,biv.y,biv.z,biv.w};
            #pragma unroll
            for (int j = 0; j < 4; j++) {
                u64 bpr, bpi, bpn;
                PK2(bpr, brs[j]); PK2(bpi, bis[j]);
                float nb = -bis[j]; PK2(bpn, nb);
                #pragma unroll
                for (int mi = 0; mi < 4; mi++) {
                    FMA2(crp[mi][j], apr[mi], bpr);
                    FMA2(crp[mi][j], api[mi], bpn);
                    FMA2(cip[mi][j], apr[mi], bpi);
                    FMA2(cip[mi][j], api[mi], bpr);
                }
            }
        }
        __syncthreads();
    }
    #pragma unroll
    for (int j = 0; j < 4; j++) {
        int jj = j0 + tx*4 + j;
        float s, c;
        sincosf(-THETAF * (float)jj, &s, &c);
        float wr = c, wi = s, curr = 1.f, curi = 0.f;
        #pragma unroll
        for (int kq = 0; kq < KH; kq++) {
            u64 cp, sp, sn;
            PK2(cp, curr); PK2(sp, curi);
            float ns = -curi; PK2(sn, ns);
            #pragma unroll
            for (int mi = 0; mi < 4; mi++) {
                int i = i0 + ty*8 + mi*2;
                int off = ((b*KH + kq)*NHh + h)*Nn + i;
                u64 ppr = *(const u64*)&g_Pr[off];
                u64 ppi = *(const u64*)&g_Pi[off];
                FMA2(crp[mi][j], ppr, cp);
                FMA2(crp[mi][j], ppi, sn);
                FMA2(cip[mi][j], ppr, sp);
                FMA2(cip[mi][j], ppi, cp);
            }
            float nr = curr*wr - curi*wi;
            curi = curr*wi + curi*wr;
            curr = nr;
        }
    }
    float* So = g_S + (size_t)(b*NHh + h)*Nn*Nn;
    #pragma unroll
    for (int r = 0; r < 8; r++) {
        int i = i0 + ty*8 + r, mi = r >> 1, hi = r & 1;
        float sv[4];
        #pragma unroll
        for (int j = 0; j < 4; j++) {
            float2 c2r = unp2(crp[mi][j]), c2i = unp2(cip[mi][j]);
            float cr = hi ? c2r.y : c2r.x, ci = hi ? c2i.y : c2i.x;
            sv[j] = sqrtf(cr*cr + ci*ci) * 0.125f;
        }
        *(float4*)&So[(size_t)i*Nn + j0 + tx*4] = make_float4(sv[0],sv[1],sv[2],sv[3]);
    }
}

// ---- k3 (2-pass): exp in place; 1/sum -> g_inv -------------------------------
__global__ void k3_softmax()
{
    __shared__ __align__(16) float red[8][33];
    int y = blockIdx.y;
    int b = y >> 3, h = y & 7;
    int tx = threadIdx.x, ty = threadIdx.y;
    int j = blockIdx.x*32 + tx;
    size_t base = (size_t)(b*NHh + h)*Nn*Nn;
    float mx = -1e30f;
    for (int i = ty; i < Nn; i += 8)
        mx = fmaxf(mx, g_S[base + (size_t)i*Nn + j]);
    red[ty][tx] = mx;
    __syncthreads();
    if (ty == 0) {
        float m = red[0][tx];
        #pragma unroll
        for (int r = 1; r < 8; r++) m = fmaxf(m, red[r][tx]);
        red[0][tx] = m;
    }
    __syncthreads();
    mx = red[0][tx];
    __syncthreads();
    float sum = 0.f;
    for (int i = ty; i < Nn; i += 8) {
        size_t o = base + (size_t)i*Nn + j;
        float e = expf(g_S[o] - mx);
        g_S[o] = e;
        sum += e;
    }
    red[ty][tx] = sum;
    __syncthreads();
    if (ty == 0) {
        float s = red[0][tx];
        #pragma unroll
        for (int r = 1; r < 8; r++) s += red[r][tx];
        g_inv[(b*NHh + h)*Nn + j] = 1.0f / s;
    }
}

// ---- k4 (mma 2-split, presplit V, ctx -> bf16 planes) ------------------------
__global__ void __launch_bounds__(512, 1) k4_mma()
{
    extern __shared__ char sm[];
    u32 smA = smem_u32(sm);
    u32 smB = smA + 4*APL;
    int tid = threadIdx.x, wid = tid >> 5, lane = tid & 31;
    int wm = wid >> 2, wn = wid & 3;
    int z = blockIdx.z, b = z >> 3, h = z & 7;
    int m0 = blockIdx.y*128, j0 = blockIdx.x*128;
    size_t vb0 = (size_t)b*KH*Dd*Nn;
    const unsigned short* Vpl[4] = {g_Vrh + vb0, g_Vrl + vb0, g_Vih + vb0, g_Vil + vb0};
    const float* S  = g_S + (size_t)(b*NHh + h)*Nn*Nn;
    const float* inv = g_inv + (b*NHh + h)*Nn;
    const int PA2[3] = {0, 0, 1};
    const int PB2[3] = {0, 1, 0};
    float dr[2][4][4] = {}, di[2][4][4] = {};
    u32 aRowOff = (u32)((wm*32 + (lane & 15))*80 + (lane >> 4)*16);
    u32 bColOff = (u32)(wn*64);

    for (int c0 = 0; c0 < Nn; c0 += 32) {
        #pragma unroll
        for (int pl = 0; pl < 4; pl++) {
            const unsigned short* src = Vpl[pl];
            #pragma unroll
            for (int it = 0; it < 2; it++) {
                int t = tid + it*512;            // 1024 tasks
                int m = t >> 3, c8 = t & 7;
                int l = m0 + m, kq = l >> 6, q = l & 63;
                size_t ro = (size_t)(kq*Dd + h*QDq + q)*Nn;
                u64 v = *(const u64*)&src[ro + c0 + c8*4];
                *(u64*)(sm + pl*APL + m*80 + c8*8) = v;
            }
        }
        #pragma unroll
        for (int it = 0; it < 2; it++) {
            int t = tid + it*512;
            int c = t >> 5, n4 = (t & 31)*4;
            float4 sv = *(const float4*)&S[(size_t)(c0 + c)*Nn + j0 + n4];
            float4 iv = *(const float4*)&inv[j0 + n4];
            unsigned short hh[4], ll[4], s2[2];
            u32 wo = (u32)(c*272 + n4*2);
            float ss[4] = {sv.x*iv.x, sv.y*iv.y, sv.z*iv.z, sv.w*iv.w};
            #pragma unroll
            for (int j = 0; j < 4; j++) { split2(ss[j], s2); hh[j]=s2[0]; ll[j]=s2[1]; }
            char* bb = sm + 4*APL;
            *(u64*)(bb + 0*BPL + wo) = (u64)hh[0] | ((u64)hh[1]<<16) | ((u64)hh[2]<<32) | ((u64)hh[3]<<48);
            *(u64*)(bb + 1*BPL + wo) = (u64)ll[0] | ((u64)ll[1]<<16) | ((u64)ll[2]<<32) | ((u64)ll[3]<<48);
        }
        __syncthreads();
        #pragma unroll
        for (int ks = 0; ks < 2; ks++) {
            #pragma unroll
            for (int s = 0; s < 3; s++) {
                u32 ar0[4], ar1[4], ai0[4], ai1[4];
                u32 abase = smA + aRowOff + (u32)(ks*32);
                LDSM4(ar0, abase + PA2[s]*APL);
                LDSM4(ar1, abase + PA2[s]*APL + 16*80);
                LDSM4(ai0, abase + (2+PA2[s])*APL);
                LDSM4(ai1, abase + (2+PA2[s])*APL + 16*80);
                u32 bbase = smB + (u32)((ks*16 + (lane & 15))*272) + bColOff;
                #pragma unroll
                for (int nt = 0; nt < 4; nt++) {
                    u32 bb[2];
                    LDSM2T(bb, bbase + (u32)(nt*16) + PB2[s]*BPL);
                    MMABF(dr[0][nt], ar0, bb); MMABF(di[0][nt], ai0, bb);
                    MMABF(dr[1][nt], ar1, bb); MMABF(di[1][nt], ai1, bb);
                }
            }
        }
        __syncthreads();
    }
    size_t cb = (size_t)b*KH*Cd*Nn;
    #pragma unroll
    for (int mt = 0; mt < 2; mt++) {
        #pragma unroll
        for (int ch = 0; ch < 2; ch++) {
            int l = m0 + wm*32 + mt*16 + (lane >> 2) + ch*8;
            int kq = l >> 6, q = l & 63;
            size_t ro = cb + (size_t)(kq*Cd + h*QDq + q)*Nn;
            #pragma unroll
            for (int nt = 0; nt < 4; nt++) {
                int j = j0 + wn*32 + nt*8 + (lane & 3)*2;
                unsigned short a2[2], b2[2];
                split2(dr[mt][nt][ch*2], a2); split2(dr[mt][nt][ch*2+1], b2);
                *(u32*)&g_Crh[ro + j] = (u32)a2[0] | ((u32)b2[0]<<16);
                *(u32*)&g_Crl[ro + j] = (u32)a2[1] | ((u32)b2[1]<<16);
                split2(di[mt][nt][ch*2], a2); split2(di[mt][nt][ch*2+1], b2);
                *(u32*)&g_Cih[ro + j] = (u32)a2[0] | ((u32)b2[0]<<16);
                *(u32*)&g_Cil[ro + j] = (u32)a2[1] | ((u32)b2[1]<<16);
            }
        }
    }
}

// ---- k5 (mma 2-split, fully presplit, real-only) -----------------------------
__global__ void __launch_bounds__(512, 1)
k5_mma(float* __restrict__ res, int n_res)
{
    extern __shared__ char sm[];
    u32 smA = smem_u32(sm);
    u32 smB = smA + 4*APL;
    int tid = threadIdx.x, wid = tid >> 5, lane = tid & 31;
    int wm = wid >> 2, wn = wid & 3;
    int z = blockIdx.z, b = z >> 2, k = z & 3;
    int m0 = blockIdx.y*128, j0 = blockIdx.x*128;
    size_t ab0 = (size_t)k*Dd*Cd;
    size_t bb0 = (size_t)b*KH*Cd*Nn + (size_t)k*Cd*Nn;
    const unsigned short* Apl[4] = {g_Orh + ab0, g_Orl + ab0, g_Onih + ab0, g_Onil + ab0};
    const unsigned short* Bpl[4] = {g_Crh + bb0, g_Crl + bb0, g_Cih + bb0, g_Cil + bb0};
    const int PA2[3] = {0, 0, 1};
    const int PB2[3] = {0, 1, 0};
    float dr[2][4][4] = {};
    u32 aRowOff = (u32)((wm*32 + (lane & 15))*80 + (lane >> 4)*16);
    u32 bColOff = (u32)(wn*64);

    for (int c0 = 0; c0 < Cd; c0 += 32) {
        #pragma unroll
        for (int pl = 0; pl < 4; pl++) {
            const unsigned short* src = Apl[pl];
            #pragma unroll
            for (int it = 0; it < 2; it++) {
                int t = tid + it*512;
                int m = t >> 3, c8 = t & 7;
                u64 v = *(const u64*)&src[(size_t)(m0+m)*Cd + c0 + c8*4];
                *(u64*)(sm + pl*APL + m*80 + c8*8) = v;
            }
        }
        #pragma unroll
        for (int pl = 0; pl < 4; pl++) {
            const unsigned short* src = Bpl[pl];
            #pragma unroll
            for (int it = 0; it < 2; it++) {
                int t = tid + it*512;
                int c = t >> 5, j8 = t & 31;
                u64 v = *(const u64*)&src[(size_t)(c0+c)*Nn + j0 + j8*4];
                *(u64*)(sm + 4*APL + pl*BPL + c*272 + j8*8) = v;
            }
        }
        __syncthreads();
        #pragma unroll
        for (int ks = 0; ks < 2; ks++) {
            #pragma unroll
            for (int s = 0; s < 3; s++) {
                u32 ar0[4], ar1[4], an0[4], an1[4];
                u32 abase = smA + aRowOff + (u32)(ks*32);
                LDSM4(ar0, abase + PA2[s]*APL);
                LDSM4(ar1, abase + PA2[s]*APL + 16*80);
                LDSM4(an0, abase + (2+PA2[s])*APL);
                LDSM4(an1, abase + (2+PA2[s])*APL + 16*80);
                u32 bbase = smB + (u32)((ks*16 + (lane & 15))*272) + bColOff;
                #pragma unroll
                for (int nt = 0; nt < 4; nt++) {
                    u32 br[2], bi2[2];
                    u32 boff = bbase + (u32)(nt*16);
                    LDSM2T(br, boff + PB2[s]*BPL);
                    LDSM2T(bi2, boff + (2+PB2[s])*BPL);
                    MMABF(dr[0][nt], ar0, br); MMABF(dr[0][nt], an0, bi2);
                    MMABF(dr[1][nt], ar1, br); MMABF(dr[1][nt], an1, bi2);
                }
            }
        }
        __syncthreads();
    }
    int nlim = n_res < OUT_ELEMS ? n_res : OUT_ELEMS;
    #pragma unroll
    for (int mt = 0; mt < 2; mt++) {
        #pragma unroll
        for (int ch = 0; ch < 2; ch++) {
            int d = m0 + wm*32 + mt*16 + (lane >> 2) + ch*8;
            size_t row = ((size_t)(b*KH + k)*Dd + d)*Nn;
            #pragma unroll
            for (int nt = 0; nt < 4; nt++) {
                int j = j0 + wn*32 + nt*8 + (lane & 3)*2;
                size_t o = row + j;
                float v0 = dr[mt][nt][ch*2], v1 = dr[mt][nt][ch*2+1];
                if (o + 2 <= (size_t)nlim) {
                    *(float2*)&res[o] = make_float2(v0, v1);
                } else {
                    if (o < (size_t)nlim) res[o] = v0;
                    if (o + 1 < (size_t)nlim) res[o+1] = v1;
                }
            }
        }
    }
}

// ---------------- launch -----------------------------------------------------
static int classify_sz(int sz, int* elems) {
    switch (sz) {
        case 8388608:  *elems = sz;   return 0;
        case 33554432: *elems = sz/4; return 0;
        case 3145728:  *elems = sz;   return 1;
        case 12582912: *elems = sz/4; return 1;
        case 2048:     *elems = sz;   return 2;
        case 8192:     *elems = sz/4; return 2;
        case 32:       *elems = sz;   return 3;
        case 128:      *elems = sz/4; return 3;
        case 1048576:  *elems = sz;   return 4;
        case 4194304:  *elems = sz/4; return 4;
        default: *elems = 0; return -1;
    }
}

extern "C" void kernel_launch(void* const* d_in, const int* in_sizes, int n_in,
                              void* d_out, int out_size)
{
    const float* pairs[5][2] = {};
    int psz[5][2] = {};
    int cnt[5] = {};
    bool ok = (n_in == 10) && d_out;
    if (ok) for (int i = 0; i < n_in; i++) if (!d_in[i]) ok = false;

    if (ok) {
        for (int i = 0; i < n_in; i++) {
            int el; int c = classify_sz(in_sizes[i], &el);
            if (c < 0 || cnt[c] >= 2) { ok = false; break; }
            pairs[c][cnt[c]] = (const float*)d_in[i];
            psz[c][cnt[c]] = el;
            cnt[c]++;
        }
        if (ok) for (int c = 0; c < 5; c++) if (cnt[c] != 2) ok = false;
    }

    const float *xr, *xi, *embr, *embi, *encr, *enci, *softr, *softi, *outr, *outi;
    int nencr, nenci, nsoftr, nsofti;
    if (ok) {
        int el0; int c0 = classify_sz(in_sizes[0], &el0);
        int ri = (c0 == 1) ? 1 : 0;
        int im = 1 - ri;
        xr    = pairs[0][ri]; xi    = pairs[0][im];
        embr  = pairs[1][ri]; embi  = pairs[1][im];
        encr  = pairs[2][ri]; nencr  = psz[2][ri]; enci  = pairs[2][im]; nenci  = psz[2][im];
        softr = pairs[3][ri]; nsoftr = psz[3][ri]; softi = pairs[3][im]; nsofti = psz[3][im];
        outr  = pairs[4][ri]; outi  = pairs[4][im];
    } else if (n_in >= 10 && d_out) {
        xr    = (const float*)d_in[0]; xi    = (const float*)d_in[1];
        embr  = (const float*)d_in[2]; embi  = (const float*)d_in[3];
        encr  = (const float*)d_in[4]; nencr  = in_sizes[4];
        enci  = (const float*)d_in[5]; nenci  = in_sizes[5];
        softr = (const float*)d_in[6]; nsoftr = in_sizes[6];
        softi = (const float*)d_in[7]; nsofti = in_sizes[7];
        outr  = (const float*)d_in[8]; outi  = (const float*)d_in[9];
    } else {
        return;
    }

    cudaFuncSetAttribute(k1_embed, cudaFuncAttributeMaxDynamicSharedMemorySize, K12_SMEM);
    cudaFuncSetAttribute(k2_scores, cudaFuncAttributeMaxDynamicSharedMemorySize, K12_SMEM);
    cudaFuncSetAttribute(k4_mma, cudaFuncAttributeMaxDynamicSharedMemorySize, K4_SMEM);
    cudaFuncSetAttribute(k5_mma, cudaFuncAttributeMaxDynamicSharedMemorySize, K5_SMEM);

    kSplitOut<<<(KH*Dd*Cd + 255)/256, 256>>>(outr, outi);
    k1_embed<<<dim3(Nn/NT, Dd/MT, 12*Bn), 256, K12_SMEM>>>(embr, embi, xr, xi, softr, softi);
    kP_pos<<<dim3(Nn/256, Bn*KH*NHh), 256>>>(encr, enci, softr, softi,
                                             nencr, nenci, nsoftr, nsofti);
    k2_scores<<<dim3(Nn/NT, Nn/MT, Bn*NHh), 256, K12_SMEM>>>();
    k3_softmax<<<dim3(Nn/32, Bn*NHh), dim3(32, 8)>>>();
    k4_mma<<<dim3(Nn/128, (KH*QDq)/128, Bn*NHh), 512, K4_SMEM>>>();
    k5_mma<<<dim3(Nn/128, Dd/128, Bn*KH), 512, K5_SMEM>>>((float*)d_out, out_size);
}